// round 14
// baseline (speedup 1.0000x reference)
#include <cuda_runtime.h>
#include <cuda_bf16.h>
#include <math_constants.h>
#include <cstdint>

#define B_  8
#define C_  256
#define L_  2048
#define D_  128
#define QK_SCALE 0.08838834764831845f  // 1/sqrt(128)

#if defined(__CUDA_ARCH_FEAT_SM103_ALL) || defined(__CUDA_ARCH_FEAT_SM101_ALL) || \
    defined(__CUDA_ARCH_FEAT_SM100_ALL) || \
    (defined(__CUDA_ARCH_SPECIFIC__) && (__CUDA_ARCH_SPECIFIC__ >= 1000))
#define HAS_TCGEN05 1
#else
#define HAS_TCGEN05 0
#endif

// ---------------- global scratch ----------------
__device__ __nv_bfloat16 g_Qhi[B_*L_*D_], g_Qlo[B_*L_*D_];
__device__ __nv_bfloat16 g_Khi[B_*L_*D_], g_Klo[B_*L_*D_];
__device__ __nv_bfloat16 g_Vthi[B_*D_*L_], g_Vtlo[B_*D_*L_];  // [B][D][L]
__device__ __nv_bfloat16 g_Xti_hi[B_*L_*C_], g_Xti_lo[B_*L_*C_];
__device__ __nv_bfloat16 g_Xto_hi[B_*L_*C_], g_Xto_lo[B_*L_*C_];
__device__ __nv_bfloat16 g_Whi[3*D_*C_], g_Wlo[3*D_*C_];

// ---------------- PTX helpers ----------------
__device__ __forceinline__ uint32_t smem_u32(const void* p) {
    uint32_t a;
    asm("{ .reg .u64 t; cvta.to.shared.u64 t, %1; cvt.u32.u64 %0, t; }"
        : "=r"(a) : "l"(p));
    return a;
}
__device__ __forceinline__ uint32_t elect_one() {
    uint32_t p;
    asm volatile("{\n\t.reg .pred p;\n\telect.sync _|p, 0xFFFFFFFF;\n\t"
                 "selp.b32 %0, 1, 0, p;\n\t}" : "=r"(p));
    return p;
}
#define TCG_ALLOC(sm, n)  asm volatile("tcgen05.alloc.cta_group::1.sync.aligned.shared::cta.b32 [%0], %1;" :: "r"(sm), "r"(n) : "memory")
#define TCG_DEALLOC(t, n) asm volatile("tcgen05.dealloc.cta_group::1.sync.aligned.b32 %0, %1;" :: "r"(t), "r"(n))
#define TCG_RELINQ()      asm volatile("tcgen05.relinquish_alloc_permit.cta_group::1.sync.aligned;")
#define TCG_COMMIT(m)     asm volatile("tcgen05.commit.cta_group::1.mbarrier::arrive::one.shared::cluster.b64 [%0];" :: "r"(m) : "memory")
#define TCG_FENCE_BEFORE() asm volatile("tcgen05.fence::before_thread_sync;" ::: "memory")
#define TCG_FENCE_AFTER()  asm volatile("tcgen05.fence::after_thread_sync;" ::: "memory")
#define TCG_WAIT_LD()     asm volatile("tcgen05.wait::ld.sync.aligned;" ::: "memory")
#define TCG_WAIT_ST()     asm volatile("tcgen05.wait::st.sync.aligned;" ::: "memory")
#define FENCE_ASYNC()     asm volatile("fence.proxy.async.shared::cta;" ::: "memory")
#define MBAR_INIT(m, c)   asm volatile("mbarrier.init.shared.b64 [%0], %1;" :: "r"(m), "r"(c) : "memory")
#define MBAR_INVAL(m)     asm volatile("mbarrier.inval.shared.b64 [%0];" :: "r"(m) : "memory")

__device__ __forceinline__ void mbar_wait(uint32_t m, uint32_t parity) {
    asm volatile(
        "{\n\t.reg .pred P1;\n\t"
        "W_%=:\n\t"
        "mbarrier.try_wait.parity.acquire.cta.shared::cta.b64 P1, [%0], %1, 0x989680;\n\t"
        "@P1 bra.uni D_%=;\n\t"
        "bra.uni W_%=;\n\t"
        "D_%=:\n\t}"
        :: "r"(m), "r"(parity) : "memory");
}

#define TCG_LD_X32(r, addr) \
    asm volatile( \
        "tcgen05.ld.sync.aligned.32x32b.x32.b32 " \
        "{%0, %1, %2, %3, %4, %5, %6, %7, " \
        " %8, %9, %10, %11, %12, %13, %14, %15, " \
        " %16, %17, %18, %19, %20, %21, %22, %23, " \
        " %24, %25, %26, %27, %28, %29, %30, %31}, [%32];" \
        : "=r"((r)[0]),  "=r"((r)[1]),  "=r"((r)[2]),  "=r"((r)[3]), \
          "=r"((r)[4]),  "=r"((r)[5]),  "=r"((r)[6]),  "=r"((r)[7]), \
          "=r"((r)[8]),  "=r"((r)[9]),  "=r"((r)[10]), "=r"((r)[11]), \
          "=r"((r)[12]), "=r"((r)[13]), "=r"((r)[14]), "=r"((r)[15]), \
          "=r"((r)[16]), "=r"((r)[17]), "=r"((r)[18]), "=r"((r)[19]), \
          "=r"((r)[20]), "=r"((r)[21]), "=r"((r)[22]), "=r"((r)[23]), \
          "=r"((r)[24]), "=r"((r)[25]), "=r"((r)[26]), "=r"((r)[27]), \
          "=r"((r)[28]), "=r"((r)[29]), "=r"((r)[30]), "=r"((r)[31]) \
        : "r"(addr))

#define TCG_ST_X32(addr, r) \
    asm volatile( \
        "tcgen05.st.sync.aligned.32x32b.x32.b32 [%0], " \
        "{%1, %2, %3, %4, %5, %6, %7, %8, " \
        " %9, %10, %11, %12, %13, %14, %15, %16, " \
        " %17, %18, %19, %20, %21, %22, %23, %24, " \
        " %25, %26, %27, %28, %29, %30, %31, %32};" \
        :: "r"(addr), \
           "r"((r)[0]),  "r"((r)[1]),  "r"((r)[2]),  "r"((r)[3]), \
           "r"((r)[4]),  "r"((r)[5]),  "r"((r)[6]),  "r"((r)[7]), \
           "r"((r)[8]),  "r"((r)[9]),  "r"((r)[10]), "r"((r)[11]), \
           "r"((r)[12]), "r"((r)[13]), "r"((r)[14]), "r"((r)[15]), \
           "r"((r)[16]), "r"((r)[17]), "r"((r)[18]), "r"((r)[19]), \
           "r"((r)[20]), "r"((r)[21]), "r"((r)[22]), "r"((r)[23]), \
           "r"((r)[24]), "r"((r)[25]), "r"((r)[26]), "r"((r)[27]), \
           "r"((r)[28]), "r"((r)[29]), "r"((r)[30]), "r"((r)[31]) \
        : "memory")

static constexpr uint64_t DESC_BASE_SW128 =
    (uint64_t(2)  << 61) | (uint64_t(1) << 46) |
    (uint64_t(64) << 32) | (uint64_t(1) << 16);
#define MK_DESC(a) (DESC_BASE_SW128 | ((uint64_t)((a) >> 4) & 0x3FFF))

__device__ __forceinline__ void mma_f16_ss(uint32_t d_tmem, uint64_t a_desc,
                                           uint64_t b_desc, uint32_t idesc,
                                           bool accum) {
#if HAS_TCGEN05
    uint32_t en = accum ? 1u : 0u;
    asm volatile(
        "{\n\t.reg .pred p;\n\tsetp.ne.u32 p, %5, 0;\n\t"
        "tcgen05.mma.cta_group::1.kind::f16 [%0], %1, %2, %3, {%4, %4, %4, %4}, p;\n\t}"
        :: "r"(d_tmem), "l"(a_desc), "l"(b_desc), "r"(idesc), "r"(0u), "r"(en)
        : "memory");
#endif
}

__device__ __forceinline__ void mma_f16_ts(uint32_t d_tmem, uint32_t a_tmem,
                                           uint64_t b_desc, uint32_t idesc,
                                           bool accum) {
#if HAS_TCGEN05
    uint32_t en = accum ? 1u : 0u;
    asm volatile(
        "{\n\t.reg .pred p;\n\tsetp.ne.u32 p, %5, 0;\n\t"
        "tcgen05.mma.cta_group::1.kind::f16 [%0], [%1], %2, %3, {%4, %4, %4, %4}, p;\n\t}"
        :: "r"(d_tmem), "r"(a_tmem), "l"(b_desc), "r"(idesc), "r"(0u), "r"(en)
        : "memory");
#endif
}

#define IDESC_128 0x8200490u   // M=128, N=128, bf16->fp32

__device__ __forceinline__ uint32_t blk_addr(int row, int c16, int rows8) {
    uint32_t byte = (uint32_t)((((row >> 3) + (c16 >> 3) * rows8) << 10)
                   + ((row & 7) << 7) + ((c16 & 7) << 4));
    return byte ^ ((byte >> 3) & 0x70);
}

__device__ __forceinline__ void split2(float a0, float a1, uint32_t& h, uint32_t& l) {
    asm("cvt.rn.bf16x2.f32 %0, %1, %2;" : "=r"(h) : "f"(a1), "f"(a0));
    float f0 = __uint_as_float(h << 16);
    float f1 = __uint_as_float(h & 0xFFFF0000u);
    float r0 = a0 - f0, r1 = a1 - f1;
    asm("cvt.rn.bf16x2.f32 %0, %1, %2;" : "=r"(l) : "f"(r1), "f"(r0));
}

// ---------------- X transpose+split (z<8, float4 loads) + W split (z==8) ----
__global__ void __launch_bounds__(256) prep_kernel(
    const float* __restrict__ x_inner, const float* __restrict__ x_outer,
    const float* __restrict__ Wq, const float* __restrict__ Wk,
    const float* __restrict__ Wv) {
    int z = blockIdx.z;
    int tid = threadIdx.x;
    if (z == 8) {
        int linear = blockIdx.y * 32 + blockIdx.x;
        if (linear >= 192) return;
        int which = linear >> 6;
        const float* W = (which == 0) ? Wq : (which == 1) ? Wk : Wv;
        int idx = ((linear & 63) * 256 + tid) * 2;
        float a0 = W[idx], a1 = W[idx + 1];
        uint32_t h, l;
        split2(a0, a1, h, l);
        *(uint32_t*)(g_Whi + which * D_ * C_ + idx) = h;
        *(uint32_t*)(g_Wlo + which * D_ * C_ + idx) = l;
        return;
    }
    int input = z >> 2, cb = z & 3;
    const float* X = input ? x_outer : x_inner;
    __nv_bfloat16* Ohi = input ? g_Xto_hi : g_Xti_hi;
    __nv_bfloat16* Olo = input ? g_Xto_lo : g_Xti_lo;
    int b = blockIdx.y;
    int l0 = blockIdx.x * 64, c0 = cb * 64;
    __shared__ float t[64][65];
    const float* Xb = X + ((size_t)b * C_ + c0) * L_ + l0;
    {
        float4 v[4];
#pragma unroll
        for (int p = 0; p < 4; ++p) {
            int e = tid + p * 256;
            int c = e >> 4, l4 = (e & 15) * 4;
            v[p] = *(const float4*)&Xb[(size_t)c * L_ + l4];
        }
#pragma unroll
        for (int p = 0; p < 4; ++p) {
            int e = tid + p * 256;
            int c = e >> 4, l4 = (e & 15) * 4;
            t[c][l4]     = v[p].x;
            t[c][l4 + 1] = v[p].y;
            t[c][l4 + 2] = v[p].z;
            t[c][l4 + 3] = v[p].w;
        }
    }
    __syncthreads();
    __nv_bfloat16* oh = Ohi + ((size_t)b * L_ + l0) * C_ + c0;
    __nv_bfloat16* ol = Olo + ((size_t)b * L_ + l0) * C_ + c0;
    for (int e = tid; e < 2048; e += 256) {
        int l = e >> 5, cp = e & 31;
        uint32_t h, lo;
        split2(t[cp * 2][l], t[cp * 2 + 1][l], h, lo);
        *(uint32_t*)(oh + (size_t)l * C_ + cp * 2) = h;
        *(uint32_t*)(ol + (size_t)l * C_ + cp * 2) = lo;
    }
}

// ---------------- fused Q/K/V tensor-core projection ----------------
// One CTA per (b, 128-l tile). 6 phases:
//  ph0: XA=Xti.h0  WB=Wq.h0   Q  = XA*WB'  (acc 0)
//  ph1: XA=Xti.h1  WB=Wq.h1   Q +=         (acc 1)
//  ph2: XA=Xto.h0  WB=Wk.h0   K  =
//  ph3:            WB=Wv.h0   V  = WB*XA'  (A/B swapped; out [d][l])
//  ph4: XA=Xto.h1  WB=Wk.h1   K +=
//  ph5:            WB=Wv.h1   V +=
// TMEM: Q cols 0..127, K 128..255, V 256..383.
#define POFF_BIAS 128
#define POFF_XA   2048
#define POFF_XAL  (POFF_XA  + 32768)
#define POFF_WH   (POFF_XAL + 32768)
#define POFF_WL   (POFF_WH + 32768)
#define PROJ_SMEM (POFF_WL + 32768)
#define VSH_STRIDE 68

__global__ void __launch_bounds__(256, 1) proj_tc_kernel(
    const float* __restrict__ bq, const float* __restrict__ bk,
    const float* __restrict__ bv) {
#if HAS_TCGEN05
    extern __shared__ char smem[];
    uint32_t sb = smem_u32(smem);
    int tid = threadIdx.x;
    int w = tid >> 5;
    int lane = tid & 31;
    int sub = w & 3;
    int ch = w >> 2;
    int row = sub * 32 + lane;
    int b = blockIdx.y;
    int l0 = blockIdx.x * 128;

    float* biasf = (float*)(smem + POFF_BIAS);
    if (tid < 128) {
        biasf[tid] = bq[tid];
        biasf[128 + tid] = bk[tid];
        biasf[256 + tid] = bv[tid];
    }

    if (w == 0) {
        TCG_ALLOC(sb + 0, 512);
        if (elect_one()) MBAR_INIT(sb + 8, 1);
    }
    __syncthreads();
    uint32_t tbase;
    asm volatile("ld.shared.b32 %0, [%1];" : "=r"(tbase) : "r"(sb + 0));
    uint32_t tmem_q = tbase, tmem_k = tbase + 128, tmem_v = tbase + 256;

    const __nv_bfloat16* XtiH = g_Xti_hi + ((size_t)b * L_ + l0) * C_;
    const __nv_bfloat16* XtiL = g_Xti_lo + ((size_t)b * L_ + l0) * C_;
    const __nv_bfloat16* XtoH = g_Xto_hi + ((size_t)b * L_ + l0) * C_;
    const __nv_bfloat16* XtoL = g_Xto_lo + ((size_t)b * L_ + l0) * C_;

    // phase tables
    const __nv_bfloat16* phAH[6] = {XtiH, XtiH, XtoH, 0, XtoH, 0};
    const __nv_bfloat16* phAL[6] = {XtiL, XtiL, XtoL, 0, XtoL, 0};
    const int phAoff[6] = {0, 128, 0, 0, 128, 0};
    const int phW[6]    = {0, 0, 1, 2, 1, 2};       // which weight
    const int phWoff[6] = {0, 128, 0, 0, 128, 128};
    const uint32_t phDst[6] = {tmem_q, tmem_q, tmem_k, tmem_v, tmem_k, tmem_v};
    const int phAcc[6]  = {0, 1, 0, 0, 1, 1};
    const int phSwap[6] = {0, 0, 0, 1, 0, 1};       // 1: A=WB, B=XA

    const int IA[3] = {0, 0, 1}, IB[3] = {0, 1, 0};

    int rr[8], cc[8];
    uint32_t aa[8];
#pragma unroll
    for (int p = 0; p < 8; ++p) {
        int i = tid + p * 256;
        rr[p] = i >> 4; cc[p] = i & 15;
        aa[p] = blk_addr(rr[p], cc[p], 16);
    }

    // ---- phase 0: direct load ----
#pragma unroll
    for (int p = 0; p < 8; ++p) {
        size_t go = (size_t)rr[p] * C_ + cc[p] * 8;
        *(uint4*)(smem + POFF_XA  + aa[p]) = *(const uint4*)(XtiH + go);
        *(uint4*)(smem + POFF_XAL + aa[p]) = *(const uint4*)(XtiL + go);
        *(uint4*)(smem + POFF_WH + aa[p]) = *(const uint4*)(g_Whi + go);
        *(uint4*)(smem + POFF_WL + aa[p]) = *(const uint4*)(g_Wlo + go);
    }
    FENCE_ASYNC();
    __syncthreads();

    for (int ph = 0; ph < 6; ++ph) {
        // issue MMA for phase ph
        if (w == 0 && elect_one()) {
            uint64_t xa[2] = {MK_DESC(sb + POFF_XA), MK_DESC(sb + POFF_XAL)};
            uint64_t wb[2] = {MK_DESC(sb + POFF_WH), MK_DESC(sb + POFF_WL)};
            uint64_t* ad = phSwap[ph] ? wb : xa;
            uint64_t* bd = phSwap[ph] ? xa : wb;
            bool acc = phAcc[ph];
#pragma unroll
            for (int p3 = 0; p3 < 3; ++p3)
#pragma unroll
                for (int ks = 0; ks < 8; ++ks) {
                    uint64_t off = (uint64_t)((ks & 3) * 2 + (ks >> 2) * 1024);
                    mma_f16_ss(phDst[ph], ad[IA[p3]] + off, bd[IB[p3]] + off,
                               IDESC_128, acc);
                    acc = true;
                }
            TCG_COMMIT(sb + 8);
        }

        if (ph == 5) break;

        // prefetch phase ph+1 into regs (overlaps MMA ph)
        int np = ph + 1;
        bool hasA = (phAH[np] != 0);
        uint4 pa[8], pal[8], pb[8], pbl[8];
        const __nv_bfloat16* WHn = g_Whi + (size_t)phW[np] * D_ * C_;
        const __nv_bfloat16* WLn = g_Wlo + (size_t)phW[np] * D_ * C_;
#pragma unroll
        for (int p = 0; p < 8; ++p) {
            size_t gw = (size_t)rr[p] * C_ + phWoff[np] + cc[p] * 8;
            pb[p]  = *(const uint4*)(WHn + gw);
            pbl[p] = *(const uint4*)(WLn + gw);
        }
        if (hasA) {
#pragma unroll
            for (int p = 0; p < 8; ++p) {
                size_t ga = (size_t)rr[p] * C_ + phAoff[np] + cc[p] * 8;
                pa[p]  = *(const uint4*)(phAH[np] + ga);
                pal[p] = *(const uint4*)(phAL[np] + ga);
            }
        }

        // wait commit ph, then store phase ph+1 tiles
        mbar_wait(sb + 8, ph & 1);
        TCG_FENCE_AFTER();
#pragma unroll
        for (int p = 0; p < 8; ++p) {
            *(uint4*)(smem + POFF_WH + aa[p]) = pb[p];
            *(uint4*)(smem + POFF_WL + aa[p]) = pbl[p];
        }
        if (hasA) {
#pragma unroll
            for (int p = 0; p < 8; ++p) {
                *(uint4*)(smem + POFF_XA  + aa[p]) = pa[p];
                *(uint4*)(smem + POFF_XAL + aa[p]) = pal[p];
            }
        }
        FENCE_ASYNC();
        __syncthreads();
    }

    // ---- epilogue: wait final commit (6 commits -> parity of commit 5 = 1) ----
    mbar_wait(sb + 8, 1);
    TCG_FENCE_AFTER();

    // Q and K: rows = l, cols = d
#pragma unroll
    for (int which = 0; which < 2; ++which) {
        float scale = (which == 0) ? QK_SCALE : 1.0f;
        __nv_bfloat16* Ohi = (which == 0) ? g_Qhi : g_Khi;
        __nv_bfloat16* Olo = (which == 0) ? g_Qlo : g_Klo;
        uint32_t tm = (which == 0) ? tmem_q : tmem_k;
        const float* bf = biasf + which * 128;
        size_t obase = ((size_t)(b * L_ + l0 + row)) * D_;
#pragma unroll
        for (int hc = 0; hc < 2; ++hc) {
            uint32_t tr[32];
            TCG_LD_X32(tr, tm + ch * 64 + hc * 32);
            TCG_WAIT_LD();
            int d0 = ch * 64 + hc * 32;
#pragma unroll
            for (int j = 0; j < 32; j += 2) {
                float a0 = (__uint_as_float(tr[j])     + bf[d0 + j])     * scale;
                float a1 = (__uint_as_float(tr[j + 1]) + bf[d0 + j + 1]) * scale;
                uint32_t h, l;
                split2(a0, a1, h, l);
                *(uint32_t*)(Ohi + obase + d0 + j) = h;
                *(uint32_t*)(Olo + obase + d0 + j) = l;
            }
        }
    }

    // V: rows = d, cols = l; stage via smem (XA region free now)
    {
        uint32_t* ShH = (uint32_t*)(smem + POFF_XA);
        uint32_t* ShL = ShH + 128 * VSH_STRIDE;
        float bv_r = biasf[256 + row];
#pragma unroll
        for (int hc = 0; hc < 2; ++hc) {
            uint32_t tr[32];
            TCG_LD_X32(tr, tmem_v + ch * 64 + hc * 32);
            TCG_WAIT_LD();
#pragma unroll
            for (int j = 0; j < 32; j += 2) {
                float a0 = __uint_as_float(tr[j])     + bv_r;
                float a1 = __uint_as_float(tr[j + 1]) + bv_r;
                uint32_t h, l;
                split2(a0, a1, h, l);
                int col = ch * 32 + hc * 16 + (j >> 1);
                ShH[row * VSH_STRIDE + col] = h;
                ShL[row * VSH_STRIDE + col] = l;
            }
        }
        TCG_FENCE_BEFORE();
        __syncthreads();
        size_t vbase = ((size_t)b * D_) * L_ + l0;
#pragma unroll
        for (int p = 0; p < 8; ++p) {
            int e = tid + p * 256;
            int r = e >> 4, q = e & 15;
            uint4 vh = *(uint4*)&ShH[r * VSH_STRIDE + q * 4];
            uint4 vl = *(uint4*)&ShL[r * VSH_STRIDE + q * 4];
            *(uint4*)(g_Vthi + vbase + (size_t)r * L_ + q * 8) = vh;
            *(uint4*)(g_Vtlo + vbase + (size_t)r * L_ + q * 8) = vl;
        }
    }

    __syncthreads();
    if (w == 0) {
        if (elect_one()) MBAR_INVAL(sb + 8);
        TCG_RELINQ();
        TCG_DEALLOC(tbase, 512);
    }
#endif
}

// ---------------- tensor-core flash attention (exact R10 version) ----------
#define OFF_RED   128
#define OFF_QHI   2048
#define OFF_QLO   (OFF_QHI + 32768)
#define OFF_KHI   (OFF_QLO + 32768)
#define OFF_KLO   (OFF_KHI + 32768)
#define OFF_VHI   (OFF_KLO + 32768)
#define OFF_VLO   (OFF_VHI + 32768)
#define FLASH_SMEM (OFF_VLO + 32768)   // 198656 bytes

#define MB_QK 8
#define MB_PV 16
#define NT 16

__global__ void __launch_bounds__(256, 1) flash_tc_kernel(float* __restrict__ Og) {
#if HAS_TCGEN05
    extern __shared__ char smem[];
    uint32_t sb = smem_u32(smem);
    int tid = threadIdx.x;
    int w = tid >> 5;
    int lane = tid & 31;
    int sub = w & 3;
    int ch = w >> 2;
    int row = sub * 32 + lane;
    int b = blockIdx.y;
    int q0 = blockIdx.x * 128;

    if (w == 0) {
        TCG_ALLOC(sb + 0, 512);
        if (elect_one()) { MBAR_INIT(sb + MB_QK, 1); MBAR_INIT(sb + MB_PV, 1); }
    }
    __syncthreads();
    uint32_t tbase;
    asm volatile("ld.shared.b32 %0, [%1];" : "=r"(tbase) : "r"(sb + 0));
    uint32_t tmem_o = tbase;
    uint32_t tmem_s[2] = {tbase + 128, tbase + 256};
    uint32_t tmem_phi = tbase + 384;
    uint32_t tmem_plo = tbase + 448;
    uint32_t wofs = (uint32_t)sub << 21;

    const int IA[3] = {0, 0, 1}, IB[3] = {0, 1, 0};
    float* redf = (float*)(smem + OFF_RED);
    const __nv_bfloat16* Kgh = g_Khi + (size_t)b * L_ * D_;
    const __nv_bfloat16* Kgl = g_Klo + (size_t)b * L_ * D_;
    size_t vtb = (size_t)b * D_ * L_;

    int rr[8], cc[8];
    uint32_t aa[8];
#pragma unroll
    for (int p = 0; p < 8; ++p) {
        int i = tid + p * 256;
        rr[p] = i >> 4; cc[p] = i & 15;
        aa[p] = blk_addr(rr[p], cc[p], 16);
    }

    {
        size_t qoff = ((size_t)(b * L_ + q0)) * D_;
#pragma unroll
        for (int p = 0; p < 8; ++p) {
            size_t go = (size_t)rr[p] * D_ + cc[p] * 8;
            *(uint4*)(smem + OFF_QHI + aa[p]) = *(const uint4*)(g_Qhi + qoff + go);
            *(uint4*)(smem + OFF_QLO + aa[p]) = *(const uint4*)(g_Qlo + qoff + go);
            *(uint4*)(smem + OFF_KHI + aa[p]) = *(const uint4*)(Kgh + go);
            *(uint4*)(smem + OFF_KLO + aa[p]) = *(const uint4*)(Kgl + go);
            size_t vo = vtb + (size_t)rr[p] * L_ + cc[p] * 8;
            *(uint4*)(smem + OFF_VHI + aa[p]) = *(const uint4*)(g_Vthi + vo);
            *(uint4*)(smem + OFF_VLO + aa[p]) = *(const uint4*)(g_Vtlo + vo);
        }
    }
    FENCE_ASYNC();
    __syncthreads();

    if (w == 0) {
        uint64_t ad[2] = {MK_DESC(sb + OFF_QHI), MK_DESC(sb + OFF_QLO)};
        uint64_t bd[2] = {MK_DESC(sb + OFF_KHI), MK_DESC(sb + OFF_KLO)};
        if (elect_one()) {
            bool acc = false;
#pragma unroll
            for (int p3 = 0; p3 < 3; ++p3)
#pragma unroll
                for (int ks = 0; ks < 8; ++ks) {
                    uint64_t off = (uint64_t)((ks & 3) * 2 + (ks >> 2) * 1024);
                    mma_f16_ss(tmem_s[0], ad[IA[p3]] + off, bd[IB[p3]] + off, IDESC_128, acc);
                    acc = true;
                }
            TCG_COMMIT(sb + MB_QK);
        }
    }

    float l_run = 0.f;

    for (int t = 0; t < NT; ++t) {
        int buf = t & 1, nbuf = buf ^ 1;

        mbar_wait(sb + MB_QK, t & 1);
        TCG_FENCE_AFTER();

        uint4 kh[8], kl[8];
        if (t < NT - 1) {
            size_t koff = (size_t)(t + 1) * 128 * D_;
#pragma unroll
            for (int p = 0; p < 8; ++p) {
                size_t go = koff + (size_t)rr[p] * D_ + cc[p] * 8;
                kh[p] = *(const uint4*)(Kgh + go);
                kl[p] = *(const uint4*)(Kgl + go);
            }
        }

        uint32_t sr[64];
        TCG_LD_X32(sr, tmem_s[buf] + ch * 64);
        TCG_LD_X32(sr + 32, tmem_s[buf] + ch * 64 + 32);

        if (t < NT - 1) {
#pragma unroll
            for (int p = 0; p < 8; ++p) {
                *(uint4*)(smem + OFF_KHI + aa[p]) = kh[p];
                *(uint4*)(smem + OFF_KLO + aa[p]) = kl[p];
            }
        }
        TCG_WAIT_LD();
        TCG_FENCE_BEFORE();
        FENCE_ASYNC();
        __syncthreads();

        if (t < NT - 1 && w == 0) {
            uint64_t ad[2] = {MK_DESC(sb + OFF_QHI), MK_DESC(sb + OFF_QLO)};
            uint64_t bd[2] = {MK_DESC(sb + OFF_KHI), MK_DESC(sb + OFF_KLO)};
            if (elect_one()) {
                bool acc = false;
#pragma unroll
                for (int p3 = 0; p3 < 3; ++p3)
#pragma unroll
                    for (int ks = 0; ks < 8; ++ks) {
                        uint64_t off = (uint64_t)((ks & 3) * 2 + (ks >> 2) * 1024);
                        mma_f16_ss(tmem_s[nbuf], ad[IA[p3]] + off, bd[IB[p3]] + off,
                                   IDESC_128, acc);
                        acc = true;
                    }
                TCG_COMMIT(sb + MB_QK);
            }
        }

        uint4 vh[8], vl[8];
        if (t >= 1) {
            size_t vo0 = vtb + (size_t)t * 128;
#pragma unroll
            for (int p = 0; p < 8; ++p) {
                size_t go = vo0 + (size_t)rr[p] * L_ + cc[p] * 8;
                vh[p] = *(const uint4*)(g_Vthi + go);
                vl[p] = *(const uint4*)(g_Vtlo + go);
            }
        }

        float lsum = 0.f;
        uint32_t hw[32], lw[32];
#pragma unroll
        for (int u = 0; u < 32; ++u) {
            float a0 = __expf(__uint_as_float(sr[u * 2]));
            float a1 = __expf(__uint_as_float(sr[u * 2 + 1]));
            lsum += a0 + a1;
            split2(a0, a1, hw[u], lw[u]);
        }
        redf[ch * 128 + row] = lsum;

        if (t >= 1) { mbar_wait(sb + MB_PV, (t - 1) & 1); TCG_FENCE_AFTER(); }

        TCG_ST_X32(tmem_phi + ch * 32 + wofs, hw);
        TCG_ST_X32(tmem_plo + ch * 32 + wofs, lw);
        TCG_WAIT_ST();
        TCG_FENCE_BEFORE();

        if (t >= 1) {
#pragma unroll
            for (int p = 0; p < 8; ++p) {
                *(uint4*)(smem + OFF_VHI + aa[p]) = vh[p];
                *(uint4*)(smem + OFF_VLO + aa[p]) = vl[p];
            }
        }
        FENCE_ASYNC();
        __syncthreads();
        l_run += redf[row] + redf[128 + row];

        if (w == 0 && elect_one()) {
            TCG_FENCE_AFTER();
            uint32_t pa[2] = {tmem_phi, tmem_plo};
            uint64_t vd[2] = {MK_DESC(sb + OFF_VHI), MK_DESC(sb + OFF_VLO)};
            bool acc = (t > 0);
#pragma unroll
            for (int p3 = 0; p3 < 3; ++p3)
#pragma unroll
                for (int ks = 0; ks < 8; ++ks) {
                    uint64_t boff = (uint64_t)((ks & 3) * 2 + (ks >> 2) * 1024);
                    mma_f16_ts(tmem_o, pa[IA[p3]] + ks * 8, vd[IB[p3]] + boff,
                               IDESC_128, acc);
                    acc = true;
                }
            TCG_COMMIT(sb + MB_PV);
        }
    }

    mbar_wait(sb + MB_PV, (NT - 1) & 1);
    TCG_FENCE_AFTER();
    {
        float inv = 1.0f / l_run;
        float* Ob = Og + ((size_t)(b * L_ + q0 + row)) * D_ + ch * 64;
        uint32_t tr[32];
        TCG_LD_X32(tr, tmem_o + ch * 64);
        TCG_WAIT_LD();
#pragma unroll
        for (int j = 0; j < 32; j += 4) {
            float4 v;
            v.x = __uint_as_float(tr[j])     * inv;
            v.y = __uint_as_float(tr[j + 1]) * inv;
            v.z = __uint_as_float(tr[j + 2]) * inv;
            v.w = __uint_as_float(tr[j + 3]) * inv;
            *(float4*)&Ob[j] = v;
        }
        TCG_LD_X32(tr, tmem_o + ch * 64 + 32);
        TCG_WAIT_LD();
#pragma unroll
        for (int j = 0; j < 32; j += 4) {
            float4 v;
            v.x = __uint_as_float(tr[j])     * inv;
            v.y = __uint_as_float(tr[j + 1]) * inv;
            v.z = __uint_as_float(tr[j + 2]) * inv;
            v.w = __uint_as_float(tr[j + 3]) * inv;
            *(float4*)&Ob[32 + j] = v;
        }
        TCG_FENCE_BEFORE();
    }

    __syncthreads();
    if (w == 0) {
        if (elect_one()) { MBAR_INVAL(sb + MB_QK); MBAR_INVAL(sb + MB_PV); }
        TCG_RELINQ();
        TCG_DEALLOC(tbase, 512);
    }
#endif  // HAS_TCGEN05
}

extern "C" void kernel_launch(void* const* d_in, const int* in_sizes, int n_in,
                              void* d_out, int out_size) {
    const float* x_inner = (const float*)d_in[0];
    const float* x_outer = (const float*)d_in[1];
    const float* Wq = (const float*)d_in[2];
    const float* bq = (const float*)d_in[3];
    const float* Wk = (const float*)d_in[4];
    const float* bk = (const float*)d_in[5];
    const float* Wv = (const float*)d_in[6];
    const float* bv = (const float*)d_in[7];
    float* out = (float*)d_out;

    cudaFuncSetAttribute(proj_tc_kernel,
                         cudaFuncAttributeMaxDynamicSharedMemorySize, PROJ_SMEM);
    cudaFuncSetAttribute(flash_tc_kernel,
                         cudaFuncAttributeMaxDynamicSharedMemorySize, FLASH_SMEM);

    prep_kernel<<<dim3(L_ / 64, B_, 9), 256>>>(x_inner, x_outer, Wq, Wk, Wv);
    proj_tc_kernel<<<dim3(L_ / 128, B_), 256, PROJ_SMEM>>>(bq, bk, bv);
    flash_tc_kernel<<<dim3(L_ / 128, B_), 256, FLASH_SMEM>>>(out);
}

// round 15
// speedup vs baseline: 1.4709x; 1.4709x over previous
#include <cuda_runtime.h>
#include <cuda_bf16.h>
#include <math_constants.h>
#include <cstdint>

#define B_  8
#define C_  256
#define L_  2048
#define D_  128
#define QK_SCALE 0.08838834764831845f  // 1/sqrt(128)

#if defined(__CUDA_ARCH_FEAT_SM103_ALL) || defined(__CUDA_ARCH_FEAT_SM101_ALL) || \
    defined(__CUDA_ARCH_FEAT_SM100_ALL) || \
    (defined(__CUDA_ARCH_SPECIFIC__) && (__CUDA_ARCH_SPECIFIC__ >= 1000))
#define HAS_TCGEN05 1
#else
#define HAS_TCGEN05 0
#endif

// ---------------- global scratch ----------------
__device__ __nv_bfloat16 g_Qhi[B_*L_*D_], g_Qlo[B_*L_*D_];
__device__ __nv_bfloat16 g_Khi[B_*L_*D_], g_Klo[B_*L_*D_];
__device__ __nv_bfloat16 g_Vthi[B_*D_*L_], g_Vtlo[B_*D_*L_];  // [B][D][L]
__device__ __nv_bfloat16 g_Xti_hi[B_*L_*C_], g_Xti_lo[B_*L_*C_];
__device__ __nv_bfloat16 g_Xto_hi[B_*L_*C_], g_Xto_lo[B_*L_*C_];
__device__ __nv_bfloat16 g_Whi[3*D_*C_], g_Wlo[3*D_*C_];

// ---------------- PTX helpers ----------------
__device__ __forceinline__ uint32_t smem_u32(const void* p) {
    uint32_t a;
    asm("{ .reg .u64 t; cvta.to.shared.u64 t, %1; cvt.u32.u64 %0, t; }"
        : "=r"(a) : "l"(p));
    return a;
}
__device__ __forceinline__ uint32_t elect_one() {
    uint32_t p;
    asm volatile("{\n\t.reg .pred p;\n\telect.sync _|p, 0xFFFFFFFF;\n\t"
                 "selp.b32 %0, 1, 0, p;\n\t}" : "=r"(p));
    return p;
}
#define TCG_ALLOC(sm, n)  asm volatile("tcgen05.alloc.cta_group::1.sync.aligned.shared::cta.b32 [%0], %1;" :: "r"(sm), "r"(n) : "memory")
#define TCG_DEALLOC(t, n) asm volatile("tcgen05.dealloc.cta_group::1.sync.aligned.b32 %0, %1;" :: "r"(t), "r"(n))
#define TCG_RELINQ()      asm volatile("tcgen05.relinquish_alloc_permit.cta_group::1.sync.aligned;")
#define TCG_COMMIT(m)     asm volatile("tcgen05.commit.cta_group::1.mbarrier::arrive::one.shared::cluster.b64 [%0];" :: "r"(m) : "memory")
#define TCG_FENCE_BEFORE() asm volatile("tcgen05.fence::before_thread_sync;" ::: "memory")
#define TCG_FENCE_AFTER()  asm volatile("tcgen05.fence::after_thread_sync;" ::: "memory")
#define TCG_WAIT_LD()     asm volatile("tcgen05.wait::ld.sync.aligned;" ::: "memory")
#define TCG_WAIT_ST()     asm volatile("tcgen05.wait::st.sync.aligned;" ::: "memory")
#define FENCE_ASYNC()     asm volatile("fence.proxy.async.shared::cta;" ::: "memory")
#define MBAR_INIT(m, c)   asm volatile("mbarrier.init.shared.b64 [%0], %1;" :: "r"(m), "r"(c) : "memory")
#define MBAR_INVAL(m)     asm volatile("mbarrier.inval.shared.b64 [%0];" :: "r"(m) : "memory")

__device__ __forceinline__ void mbar_wait(uint32_t m, uint32_t parity) {
    asm volatile(
        "{\n\t.reg .pred P1;\n\t"
        "W_%=:\n\t"
        "mbarrier.try_wait.parity.acquire.cta.shared::cta.b64 P1, [%0], %1, 0x989680;\n\t"
        "@P1 bra.uni D_%=;\n\t"
        "bra.uni W_%=;\n\t"
        "D_%=:\n\t}"
        :: "r"(m), "r"(parity) : "memory");
}

#define TCG_LD_X32(r, addr) \
    asm volatile( \
        "tcgen05.ld.sync.aligned.32x32b.x32.b32 " \
        "{%0, %1, %2, %3, %4, %5, %6, %7, " \
        " %8, %9, %10, %11, %12, %13, %14, %15, " \
        " %16, %17, %18, %19, %20, %21, %22, %23, " \
        " %24, %25, %26, %27, %28, %29, %30, %31}, [%32];" \
        : "=r"((r)[0]),  "=r"((r)[1]),  "=r"((r)[2]),  "=r"((r)[3]), \
          "=r"((r)[4]),  "=r"((r)[5]),  "=r"((r)[6]),  "=r"((r)[7]), \
          "=r"((r)[8]),  "=r"((r)[9]),  "=r"((r)[10]), "=r"((r)[11]), \
          "=r"((r)[12]), "=r"((r)[13]), "=r"((r)[14]), "=r"((r)[15]), \
          "=r"((r)[16]), "=r"((r)[17]), "=r"((r)[18]), "=r"((r)[19]), \
          "=r"((r)[20]), "=r"((r)[21]), "=r"((r)[22]), "=r"((r)[23]), \
          "=r"((r)[24]), "=r"((r)[25]), "=r"((r)[26]), "=r"((r)[27]), \
          "=r"((r)[28]), "=r"((r)[29]), "=r"((r)[30]), "=r"((r)[31]) \
        : "r"(addr))

#define TCG_ST_X32(addr, r) \
    asm volatile( \
        "tcgen05.st.sync.aligned.32x32b.x32.b32 [%0], " \
        "{%1, %2, %3, %4, %5, %6, %7, %8, " \
        " %9, %10, %11, %12, %13, %14, %15, %16, " \
        " %17, %18, %19, %20, %21, %22, %23, %24, " \
        " %25, %26, %27, %28, %29, %30, %31, %32};" \
        :: "r"(addr), \
           "r"((r)[0]),  "r"((r)[1]),  "r"((r)[2]),  "r"((r)[3]), \
           "r"((r)[4]),  "r"((r)[5]),  "r"((r)[6]),  "r"((r)[7]), \
           "r"((r)[8]),  "r"((r)[9]),  "r"((r)[10]), "r"((r)[11]), \
           "r"((r)[12]), "r"((r)[13]), "r"((r)[14]), "r"((r)[15]), \
           "r"((r)[16]), "r"((r)[17]), "r"((r)[18]), "r"((r)[19]), \
           "r"((r)[20]), "r"((r)[21]), "r"((r)[22]), "r"((r)[23]), \
           "r"((r)[24]), "r"((r)[25]), "r"((r)[26]), "r"((r)[27]), \
           "r"((r)[28]), "r"((r)[29]), "r"((r)[30]), "r"((r)[31]) \
        : "memory")

static constexpr uint64_t DESC_BASE_SW128 =
    (uint64_t(2)  << 61) | (uint64_t(1) << 46) |
    (uint64_t(64) << 32) | (uint64_t(1) << 16);
#define MK_DESC(a) (DESC_BASE_SW128 | ((uint64_t)((a) >> 4) & 0x3FFF))

__device__ __forceinline__ void mma_f16_ss(uint32_t d_tmem, uint64_t a_desc,
                                           uint64_t b_desc, uint32_t idesc,
                                           bool accum) {
#if HAS_TCGEN05
    uint32_t en = accum ? 1u : 0u;
    asm volatile(
        "{\n\t.reg .pred p;\n\tsetp.ne.u32 p, %5, 0;\n\t"
        "tcgen05.mma.cta_group::1.kind::f16 [%0], %1, %2, %3, {%4, %4, %4, %4}, p;\n\t}"
        :: "r"(d_tmem), "l"(a_desc), "l"(b_desc), "r"(idesc), "r"(0u), "r"(en)
        : "memory");
#endif
}

__device__ __forceinline__ void mma_f16_ts(uint32_t d_tmem, uint32_t a_tmem,
                                           uint64_t b_desc, uint32_t idesc,
                                           bool accum) {
#if HAS_TCGEN05
    uint32_t en = accum ? 1u : 0u;
    asm volatile(
        "{\n\t.reg .pred p;\n\tsetp.ne.u32 p, %5, 0;\n\t"
        "tcgen05.mma.cta_group::1.kind::f16 [%0], [%1], %2, %3, {%4, %4, %4, %4}, p;\n\t}"
        :: "r"(d_tmem), "r"(a_tmem), "l"(b_desc), "r"(idesc), "r"(0u), "r"(en)
        : "memory");
#endif
}

#define IDESC_128 0x8200490u   // M=128, N=128, bf16->fp32

__device__ __forceinline__ uint32_t blk_addr(int row, int c16, int rows8) {
    uint32_t byte = (uint32_t)((((row >> 3) + (c16 >> 3) * rows8) << 10)
                   + ((row & 7) << 7) + ((c16 & 7) << 4));
    return byte ^ ((byte >> 3) & 0x70);
}

__device__ __forceinline__ void split2(float a0, float a1, uint32_t& h, uint32_t& l) {
    asm("cvt.rn.bf16x2.f32 %0, %1, %2;" : "=r"(h) : "f"(a1), "f"(a0));
    float f0 = __uint_as_float(h << 16);
    float f1 = __uint_as_float(h & 0xFFFF0000u);
    float r0 = a0 - f0, r1 = a1 - f1;
    asm("cvt.rn.bf16x2.f32 %0, %1, %2;" : "=r"(l) : "f"(r1), "f"(r0));
}

// ---------------- X transpose+split (z<8, float4 loads) + W split (z==8) ----
__global__ void __launch_bounds__(256) prep_kernel(
    const float* __restrict__ x_inner, const float* __restrict__ x_outer,
    const float* __restrict__ Wq, const float* __restrict__ Wk,
    const float* __restrict__ Wv) {
    int z = blockIdx.z;
    int tid = threadIdx.x;
    if (z == 8) {
        int linear = blockIdx.y * 32 + blockIdx.x;
        if (linear >= 192) return;
        int which = linear >> 6;
        const float* W = (which == 0) ? Wq : (which == 1) ? Wk : Wv;
        int idx = ((linear & 63) * 256 + tid) * 2;
        float a0 = W[idx], a1 = W[idx + 1];
        uint32_t h, l;
        split2(a0, a1, h, l);
        *(uint32_t*)(g_Whi + which * D_ * C_ + idx) = h;
        *(uint32_t*)(g_Wlo + which * D_ * C_ + idx) = l;
        return;
    }
    int input = z >> 2, cb = z & 3;
    const float* X = input ? x_outer : x_inner;
    __nv_bfloat16* Ohi = input ? g_Xto_hi : g_Xti_hi;
    __nv_bfloat16* Olo = input ? g_Xto_lo : g_Xti_lo;
    int b = blockIdx.y;
    int l0 = blockIdx.x * 64, c0 = cb * 64;
    __shared__ float t[64][65];
    const float* Xb = X + ((size_t)b * C_ + c0) * L_ + l0;
    {
        float4 v[4];
#pragma unroll
        for (int p = 0; p < 4; ++p) {
            int e = tid + p * 256;
            int c = e >> 4, l4 = (e & 15) * 4;
            v[p] = *(const float4*)&Xb[(size_t)c * L_ + l4];
        }
#pragma unroll
        for (int p = 0; p < 4; ++p) {
            int e = tid + p * 256;
            int c = e >> 4, l4 = (e & 15) * 4;
            t[c][l4]     = v[p].x;
            t[c][l4 + 1] = v[p].y;
            t[c][l4 + 2] = v[p].z;
            t[c][l4 + 3] = v[p].w;
        }
    }
    __syncthreads();
    __nv_bfloat16* oh = Ohi + ((size_t)b * L_ + l0) * C_ + c0;
    __nv_bfloat16* ol = Olo + ((size_t)b * L_ + l0) * C_ + c0;
    for (int e = tid; e < 2048; e += 256) {
        int l = e >> 5, cp = e & 31;
        uint32_t h, lo;
        split2(t[cp * 2][l], t[cp * 2 + 1][l], h, lo);
        *(uint32_t*)(oh + (size_t)l * C_ + cp * 2) = h;
        *(uint32_t*)(ol + (size_t)l * C_ + cp * 2) = lo;
    }
}

// ---------------- tensor-core projection (R13 + half-1 B front-batch) -------
#define POFF_BIAS 128
#define POFF_A    1024
#define POFF_AL   (POFF_A  + 32768)
#define POFF_WH   (POFF_AL + 32768)
#define POFF_WL   (POFF_WH + 32768)
#define PROJ_SMEM (POFF_WL + 32768)
#define VSH_STRIDE 68

__global__ void __launch_bounds__(256, 1) proj_tc_kernel(
    const float* __restrict__ bq, const float* __restrict__ bk,
    const float* __restrict__ bv) {
#if HAS_TCGEN05
    extern __shared__ char smem[];
    uint32_t sb = smem_u32(smem);
    int tid = threadIdx.x;
    int w = tid >> 5;
    int lane = tid & 31;
    int sub = w & 3;
    int ch = w >> 2;
    int row = sub * 32 + lane;
    int which = blockIdx.z;
    int b = blockIdx.y;
    int l0 = blockIdx.x * 128;

    const float* bias = (which == 0) ? bq : (which == 1) ? bk : bv;
    float* biasf = (float*)(smem + POFF_BIAS);
    if (tid < 128) biasf[tid] = bias[tid];

    if (w == 0) {
        TCG_ALLOC(sb + 0, 128);
        if (elect_one()) MBAR_INIT(sb + 8, 1);
    }
    __syncthreads();
    uint32_t tbase;
    asm volatile("ld.shared.b32 %0, [%1];" : "=r"(tbase) : "r"(sb + 0));

    const __nv_bfloat16 *Ah, *Al, *Bh, *Bl;
    if (which == 2) {
        Ah = g_Whi + 2 * D_ * C_;
        Al = g_Wlo + 2 * D_ * C_;
        Bh = g_Xto_hi + ((size_t)b * L_ + l0) * C_;
        Bl = g_Xto_lo + ((size_t)b * L_ + l0) * C_;
    } else {
        Ah = ((which == 0) ? g_Xti_hi : g_Xto_hi) + ((size_t)b * L_ + l0) * C_;
        Al = ((which == 0) ? g_Xti_lo : g_Xto_lo) + ((size_t)b * L_ + l0) * C_;
        Bh = g_Whi + (size_t)which * D_ * C_;
        Bl = g_Wlo + (size_t)which * D_ * C_;
    }

    const int IA[3] = {0, 0, 1}, IB[3] = {0, 1, 0};

    int rr[8], cc[8];
    uint32_t aa[8];
#pragma unroll
    for (int p = 0; p < 8; ++p) {
        int i = tid + p * 256;
        rr[p] = i >> 4; cc[p] = i & 15;
        aa[p] = blk_addr(rr[p], cc[p], 16);
    }

    // ---- half 0: load + MMA ----
#pragma unroll
    for (int p = 0; p < 8; ++p) {
        size_t go = (size_t)rr[p] * C_ + cc[p] * 8;
        *(uint4*)(smem + POFF_A  + aa[p]) = *(const uint4*)(Ah + go);
        *(uint4*)(smem + POFF_AL + aa[p]) = *(const uint4*)(Al + go);
        *(uint4*)(smem + POFF_WH + aa[p]) = *(const uint4*)(Bh + go);
        *(uint4*)(smem + POFF_WL + aa[p]) = *(const uint4*)(Bl + go);
    }
    FENCE_ASYNC();
    __syncthreads();
    if (w == 0) {
        uint64_t ad[2] = {MK_DESC(sb + POFF_A),  MK_DESC(sb + POFF_AL)};
        uint64_t bd[2] = {MK_DESC(sb + POFF_WH), MK_DESC(sb + POFF_WL)};
        if (elect_one()) {
            bool acc = false;
#pragma unroll
            for (int p3 = 0; p3 < 3; ++p3)
#pragma unroll
                for (int ks = 0; ks < 8; ++ks) {
                    uint64_t off = (uint64_t)((ks & 3) * 2 + (ks >> 2) * 1024);
                    mma_f16_ss(tbase, ad[IA[p3]] + off, bd[IB[p3]] + off, IDESC_128, acc);
                    acc = true;
                }
            TCG_COMMIT(sb + 8);
        }
    }

    // ---- prefetch half-1 A tiles into regs while MMA0 runs ----
    uint4 pah[8], pal[8];
#pragma unroll
    for (int p = 0; p < 8; ++p) {
        size_t go = (size_t)rr[p] * C_ + 128 + cc[p] * 8;
        pah[p] = *(const uint4*)(Ah + go);
        pal[p] = *(const uint4*)(Al + go);
    }

    mbar_wait(sb + 8, 0);
    TCG_FENCE_AFTER();

    // ---- half 1: front-batch B LDGs (latency hides under A stores), then
    //      store A, store B, MMA ----
    {
        uint4 pbh[8], pbl[8];
#pragma unroll
        for (int p = 0; p < 8; ++p) {
            size_t go = (size_t)rr[p] * C_ + 128 + cc[p] * 8;
            pbh[p] = *(const uint4*)(Bh + go);
            pbl[p] = *(const uint4*)(Bl + go);
        }
#pragma unroll
        for (int p = 0; p < 8; ++p) {
            *(uint4*)(smem + POFF_A  + aa[p]) = pah[p];
            *(uint4*)(smem + POFF_AL + aa[p]) = pal[p];
        }
#pragma unroll
        for (int p = 0; p < 8; ++p) {
            *(uint4*)(smem + POFF_WH + aa[p]) = pbh[p];
            *(uint4*)(smem + POFF_WL + aa[p]) = pbl[p];
        }
    }
    FENCE_ASYNC();
    __syncthreads();
    if (w == 0) {
        uint64_t ad[2] = {MK_DESC(sb + POFF_A),  MK_DESC(sb + POFF_AL)};
        uint64_t bd[2] = {MK_DESC(sb + POFF_WH), MK_DESC(sb + POFF_WL)};
        if (elect_one()) {
            bool acc = true;
#pragma unroll
            for (int p3 = 0; p3 < 3; ++p3)
#pragma unroll
                for (int ks = 0; ks < 8; ++ks) {
                    uint64_t off = (uint64_t)((ks & 3) * 2 + (ks >> 2) * 1024);
                    mma_f16_ss(tbase, ad[IA[p3]] + off, bd[IB[p3]] + off, IDESC_128, acc);
                }
            TCG_COMMIT(sb + 8);
        }
    }

    mbar_wait(sb + 8, 1);
    TCG_FENCE_AFTER();
    if (which != 2) {
        float scale = (which == 0) ? QK_SCALE : 1.0f;
        __nv_bfloat16* Ohi = (which == 0) ? g_Qhi : g_Khi;
        __nv_bfloat16* Olo = (which == 0) ? g_Qlo : g_Klo;
        size_t obase = ((size_t)(b * L_ + l0 + row)) * D_;
#pragma unroll
        for (int hc = 0; hc < 2; ++hc) {
            uint32_t tr[32];
            TCG_LD_X32(tr, tbase + ch * 64 + hc * 32);
            TCG_WAIT_LD();
            int d0 = ch * 64 + hc * 32;
#pragma unroll
            for (int j = 0; j < 32; j += 2) {
                float a0 = (__uint_as_float(tr[j])     + biasf[d0 + j])     * scale;
                float a1 = (__uint_as_float(tr[j + 1]) + biasf[d0 + j + 1]) * scale;
                uint32_t h, l;
                split2(a0, a1, h, l);
                *(uint32_t*)(Ohi + obase + d0 + j) = h;
                *(uint32_t*)(Olo + obase + d0 + j) = l;
            }
        }
        TCG_FENCE_BEFORE();
    } else {
        uint32_t* ShH = (uint32_t*)(smem + POFF_A);
        uint32_t* ShL = ShH + 128 * VSH_STRIDE;
        float bv_r = biasf[row];
#pragma unroll
        for (int hc = 0; hc < 2; ++hc) {
            uint32_t tr[32];
            TCG_LD_X32(tr, tbase + ch * 64 + hc * 32);
            TCG_WAIT_LD();
#pragma unroll
            for (int j = 0; j < 32; j += 2) {
                float a0 = __uint_as_float(tr[j])     + bv_r;
                float a1 = __uint_as_float(tr[j + 1]) + bv_r;
                uint32_t h, l;
                split2(a0, a1, h, l);
                int col = ch * 32 + hc * 16 + (j >> 1);
                ShH[row * VSH_STRIDE + col] = h;
                ShL[row * VSH_STRIDE + col] = l;
            }
        }
        TCG_FENCE_BEFORE();
        __syncthreads();
        size_t vbase = ((size_t)b * D_) * L_ + l0;
#pragma unroll
        for (int p = 0; p < 8; ++p) {
            int e = tid + p * 256;
            int r = e >> 4, q = e & 15;
            uint4 vh = *(uint4*)&ShH[r * VSH_STRIDE + q * 4];
            uint4 vl = *(uint4*)&ShL[r * VSH_STRIDE + q * 4];
            *(uint4*)(g_Vthi + vbase + (size_t)r * L_ + q * 8) = vh;
            *(uint4*)(g_Vtlo + vbase + (size_t)r * L_ + q * 8) = vl;
        }
    }

    __syncthreads();
    if (w == 0) {
        if (elect_one()) MBAR_INVAL(sb + 8);
        TCG_RELINQ();
        TCG_DEALLOC(tbase, 128);
    }
#endif
}

// ---------------- tensor-core flash attention (exact R10 version) ----------
#define OFF_RED   128
#define OFF_QHI   2048
#define OFF_QLO   (OFF_QHI + 32768)
#define OFF_KHI   (OFF_QLO + 32768)
#define OFF_KLO   (OFF_KHI + 32768)
#define OFF_VHI   (OFF_KLO + 32768)
#define OFF_VLO   (OFF_VHI + 32768)
#define FLASH_SMEM (OFF_VLO + 32768)   // 198656 bytes

#define MB_QK 8
#define MB_PV 16
#define NT 16

__global__ void __launch_bounds__(256, 1) flash_tc_kernel(float* __restrict__ Og) {
#if HAS_TCGEN05
    extern __shared__ char smem[];
    uint32_t sb = smem_u32(smem);
    int tid = threadIdx.x;
    int w = tid >> 5;
    int lane = tid & 31;
    int sub = w & 3;
    int ch = w >> 2;
    int row = sub * 32 + lane;
    int b = blockIdx.y;
    int q0 = blockIdx.x * 128;

    if (w == 0) {
        TCG_ALLOC(sb + 0, 512);
        if (elect_one()) { MBAR_INIT(sb + MB_QK, 1); MBAR_INIT(sb + MB_PV, 1); }
    }
    __syncthreads();
    uint32_t tbase;
    asm volatile("ld.shared.b32 %0, [%1];" : "=r"(tbase) : "r"(sb + 0));
    uint32_t tmem_o = tbase;
    uint32_t tmem_s[2] = {tbase + 128, tbase + 256};
    uint32_t tmem_phi = tbase + 384;
    uint32_t tmem_plo = tbase + 448;
    uint32_t wofs = (uint32_t)sub << 21;

    const int IA[3] = {0, 0, 1}, IB[3] = {0, 1, 0};
    float* redf = (float*)(smem + OFF_RED);
    const __nv_bfloat16* Kgh = g_Khi + (size_t)b * L_ * D_;
    const __nv_bfloat16* Kgl = g_Klo + (size_t)b * L_ * D_;
    size_t vtb = (size_t)b * D_ * L_;

    int rr[8], cc[8];
    uint32_t aa[8];
#pragma unroll
    for (int p = 0; p < 8; ++p) {
        int i = tid + p * 256;
        rr[p] = i >> 4; cc[p] = i & 15;
        aa[p] = blk_addr(rr[p], cc[p], 16);
    }

    {
        size_t qoff = ((size_t)(b * L_ + q0)) * D_;
#pragma unroll
        for (int p = 0; p < 8; ++p) {
            size_t go = (size_t)rr[p] * D_ + cc[p] * 8;
            *(uint4*)(smem + OFF_QHI + aa[p]) = *(const uint4*)(g_Qhi + qoff + go);
            *(uint4*)(smem + OFF_QLO + aa[p]) = *(const uint4*)(g_Qlo + qoff + go);
            *(uint4*)(smem + OFF_KHI + aa[p]) = *(const uint4*)(Kgh + go);
            *(uint4*)(smem + OFF_KLO + aa[p]) = *(const uint4*)(Kgl + go);
            size_t vo = vtb + (size_t)rr[p] * L_ + cc[p] * 8;
            *(uint4*)(smem + OFF_VHI + aa[p]) = *(const uint4*)(g_Vthi + vo);
            *(uint4*)(smem + OFF_VLO + aa[p]) = *(const uint4*)(g_Vtlo + vo);
        }
    }
    FENCE_ASYNC();
    __syncthreads();

    if (w == 0) {
        uint64_t ad[2] = {MK_DESC(sb + OFF_QHI), MK_DESC(sb + OFF_QLO)};
        uint64_t bd[2] = {MK_DESC(sb + OFF_KHI), MK_DESC(sb + OFF_KLO)};
        if (elect_one()) {
            bool acc = false;
#pragma unroll
            for (int p3 = 0; p3 < 3; ++p3)
#pragma unroll
                for (int ks = 0; ks < 8; ++ks) {
                    uint64_t off = (uint64_t)((ks & 3) * 2 + (ks >> 2) * 1024);
                    mma_f16_ss(tmem_s[0], ad[IA[p3]] + off, bd[IB[p3]] + off, IDESC_128, acc);
                    acc = true;
                }
            TCG_COMMIT(sb + MB_QK);
        }
    }

    float l_run = 0.f;

    for (int t = 0; t < NT; ++t) {
        int buf = t & 1, nbuf = buf ^ 1;

        mbar_wait(sb + MB_QK, t & 1);
        TCG_FENCE_AFTER();

        uint4 kh[8], kl[8];
        if (t < NT - 1) {
            size_t koff = (size_t)(t + 1) * 128 * D_;
#pragma unroll
            for (int p = 0; p < 8; ++p) {
                size_t go = koff + (size_t)rr[p] * D_ + cc[p] * 8;
                kh[p] = *(const uint4*)(Kgh + go);
                kl[p] = *(const uint4*)(Kgl + go);
            }
        }

        uint32_t sr[64];
        TCG_LD_X32(sr, tmem_s[buf] + ch * 64);
        TCG_LD_X32(sr + 32, tmem_s[buf] + ch * 64 + 32);

        if (t < NT - 1) {
#pragma unroll
            for (int p = 0; p < 8; ++p) {
                *(uint4*)(smem + OFF_KHI + aa[p]) = kh[p];
                *(uint4*)(smem + OFF_KLO + aa[p]) = kl[p];
            }
        }
        TCG_WAIT_LD();
        TCG_FENCE_BEFORE();
        FENCE_ASYNC();
        __syncthreads();

        if (t < NT - 1 && w == 0) {
            uint64_t ad[2] = {MK_DESC(sb + OFF_QHI), MK_DESC(sb + OFF_QLO)};
            uint64_t bd[2] = {MK_DESC(sb + OFF_KHI), MK_DESC(sb + OFF_KLO)};
            if (elect_one()) {
                bool acc = false;
#pragma unroll
                for (int p3 = 0; p3 < 3; ++p3)
#pragma unroll
                    for (int ks = 0; ks < 8; ++ks) {
                        uint64_t off = (uint64_t)((ks & 3) * 2 + (ks >> 2) * 1024);
                        mma_f16_ss(tmem_s[nbuf], ad[IA[p3]] + off, bd[IB[p3]] + off,
                                   IDESC_128, acc);
                        acc = true;
                    }
                TCG_COMMIT(sb + MB_QK);
            }
        }

        uint4 vh[8], vl[8];
        if (t >= 1) {
            size_t vo0 = vtb + (size_t)t * 128;
#pragma unroll
            for (int p = 0; p < 8; ++p) {
                size_t go = vo0 + (size_t)rr[p] * L_ + cc[p] * 8;
                vh[p] = *(const uint4*)(g_Vthi + go);
                vl[p] = *(const uint4*)(g_Vtlo + go);
            }
        }

        float lsum = 0.f;
        uint32_t hw[32], lw[32];
#pragma unroll
        for (int u = 0; u < 32; ++u) {
            float a0 = __expf(__uint_as_float(sr[u * 2]));
            float a1 = __expf(__uint_as_float(sr[u * 2 + 1]));
            lsum += a0 + a1;
            split2(a0, a1, hw[u], lw[u]);
        }
        redf[ch * 128 + row] = lsum;

        if (t >= 1) { mbar_wait(sb + MB_PV, (t - 1) & 1); TCG_FENCE_AFTER(); }

        TCG_ST_X32(tmem_phi + ch * 32 + wofs, hw);
        TCG_ST_X32(tmem_plo + ch * 32 + wofs, lw);
        TCG_WAIT_ST();
        TCG_FENCE_BEFORE();

        if (t >= 1) {
#pragma unroll
            for (int p = 0; p < 8; ++p) {
                *(uint4*)(smem + OFF_VHI + aa[p]) = vh[p];
                *(uint4*)(smem + OFF_VLO + aa[p]) = vl[p];
            }
        }
        FENCE_ASYNC();
        __syncthreads();
        l_run += redf[row] + redf[128 + row];

        if (w == 0 && elect_one()) {
            TCG_FENCE_AFTER();
            uint32_t pa[2] = {tmem_phi, tmem_plo};
            uint64_t vd[2] = {MK_DESC(sb + OFF_VHI), MK_DESC(sb + OFF_VLO)};
            bool acc = (t > 0);
#pragma unroll
            for (int p3 = 0; p3 < 3; ++p3)
#pragma unroll
                for (int ks = 0; ks < 8; ++ks) {
                    uint64_t boff = (uint64_t)((ks & 3) * 2 + (ks >> 2) * 1024);
                    mma_f16_ts(tmem_o, pa[IA[p3]] + ks * 8, vd[IB[p3]] + boff,
                               IDESC_128, acc);
                    acc = true;
                }
            TCG_COMMIT(sb + MB_PV);
        }
    }

    mbar_wait(sb + MB_PV, (NT - 1) & 1);
    TCG_FENCE_AFTER();
    {
        float inv = 1.0f / l_run;
        float* Ob = Og + ((size_t)(b * L_ + q0 + row)) * D_ + ch * 64;
        uint32_t tr[32];
        TCG_LD_X32(tr, tmem_o + ch * 64);
        TCG_WAIT_LD();
#pragma unroll
        for (int j = 0; j < 32; j += 4) {
            float4 v;
            v.x = __uint_as_float(tr[j])     * inv;
            v.y = __uint_as_float(tr[j + 1]) * inv;
            v.z = __uint_as_float(tr[j + 2]) * inv;
            v.w = __uint_as_float(tr[j + 3]) * inv;
            *(float4*)&Ob[j] = v;
        }
        TCG_LD_X32(tr, tmem_o + ch * 64 + 32);
        TCG_WAIT_LD();
#pragma unroll
        for (int j = 0; j < 32; j += 4) {
            float4 v;
            v.x = __uint_as_float(tr[j])     * inv;
            v.y = __uint_as_float(tr[j + 1]) * inv;
            v.z = __uint_as_float(tr[j + 2]) * inv;
            v.w = __uint_as_float(tr[j + 3]) * inv;
            *(float4*)&Ob[32 + j] = v;
        }
        TCG_FENCE_BEFORE();
    }

    __syncthreads();
    if (w == 0) {
        if (elect_one()) { MBAR_INVAL(sb + MB_QK); MBAR_INVAL(sb + MB_PV); }
        TCG_RELINQ();
        TCG_DEALLOC(tbase, 512);
    }
#endif  // HAS_TCGEN05
}

extern "C" void kernel_launch(void* const* d_in, const int* in_sizes, int n_in,
                              void* d_out, int out_size) {
    const float* x_inner = (const float*)d_in[0];
    const float* x_outer = (const float*)d_in[1];
    const float* Wq = (const float*)d_in[2];
    const float* bq = (const float*)d_in[3];
    const float* Wk = (const float*)d_in[4];
    const float* bk = (const float*)d_in[5];
    const float* Wv = (const float*)d_in[6];
    const float* bv = (const float*)d_in[7];
    float* out = (float*)d_out;

    cudaFuncSetAttribute(proj_tc_kernel,
                         cudaFuncAttributeMaxDynamicSharedMemorySize, PROJ_SMEM);
    cudaFuncSetAttribute(flash_tc_kernel,
                         cudaFuncAttributeMaxDynamicSharedMemorySize, FLASH_SMEM);

    prep_kernel<<<dim3(L_ / 64, B_, 9), 256>>>(x_inner, x_outer, Wq, Wk, Wv);
    proj_tc_kernel<<<dim3(L_ / 128, B_, 3), 256, PROJ_SMEM>>>(bq, bk, bv);
    flash_tc_kernel<<<dim3(L_ / 128, B_), 256, FLASH_SMEM>>>(out);
}

// round 16
// speedup vs baseline: 1.5301x; 1.0402x over previous
#include <cuda_runtime.h>
#include <cuda_bf16.h>
#include <math_constants.h>
#include <cstdint>

#define B_  8
#define C_  256
#define L_  2048
#define D_  128
#define QK_SCALE 0.08838834764831845f  // 1/sqrt(128)
#define LOG2E    1.4426950408889634f

#if defined(__CUDA_ARCH_FEAT_SM103_ALL) || defined(__CUDA_ARCH_FEAT_SM101_ALL) || \
    defined(__CUDA_ARCH_FEAT_SM100_ALL) || \
    (defined(__CUDA_ARCH_SPECIFIC__) && (__CUDA_ARCH_SPECIFIC__ >= 1000))
#define HAS_TCGEN05 1
#else
#define HAS_TCGEN05 0
#endif

#if defined(__CUDA_ARCH__) && (__CUDA_ARCH__ >= 900)
#define GRID_DEP_SYNC()  cudaGridDependencySynchronize()
#define GRID_TRIGGER()   cudaTriggerProgrammaticLaunchCompletion()
#else
#define GRID_DEP_SYNC()
#define GRID_TRIGGER()
#endif

// ---------------- global scratch ----------------
__device__ __nv_bfloat16 g_Qhi[B_*L_*D_], g_Qlo[B_*L_*D_];
__device__ __nv_bfloat16 g_Khi[B_*L_*D_], g_Klo[B_*L_*D_];
__device__ __nv_bfloat16 g_Vthi[B_*D_*L_], g_Vtlo[B_*D_*L_];  // [B][D][L]
__device__ __nv_bfloat16 g_Xti_hi[B_*L_*C_], g_Xti_lo[B_*L_*C_];
__device__ __nv_bfloat16 g_Xto_hi[B_*L_*C_], g_Xto_lo[B_*L_*C_];
__device__ __nv_bfloat16 g_Whi[3*D_*C_], g_Wlo[3*D_*C_];

// ---------------- PTX helpers ----------------
__device__ __forceinline__ uint32_t smem_u32(const void* p) {
    uint32_t a;
    asm("{ .reg .u64 t; cvta.to.shared.u64 t, %1; cvt.u32.u64 %0, t; }"
        : "=r"(a) : "l"(p));
    return a;
}
__device__ __forceinline__ uint32_t elect_one() {
    uint32_t p;
    asm volatile("{\n\t.reg .pred p;\n\telect.sync _|p, 0xFFFFFFFF;\n\t"
                 "selp.b32 %0, 1, 0, p;\n\t}" : "=r"(p));
    return p;
}
#define TCG_ALLOC(sm, n)  asm volatile("tcgen05.alloc.cta_group::1.sync.aligned.shared::cta.b32 [%0], %1;" :: "r"(sm), "r"(n) : "memory")
#define TCG_DEALLOC(t, n) asm volatile("tcgen05.dealloc.cta_group::1.sync.aligned.b32 %0, %1;" :: "r"(t), "r"(n))
#define TCG_RELINQ()      asm volatile("tcgen05.relinquish_alloc_permit.cta_group::1.sync.aligned;")
#define TCG_COMMIT(m)     asm volatile("tcgen05.commit.cta_group::1.mbarrier::arrive::one.shared::cluster.b64 [%0];" :: "r"(m) : "memory")
#define TCG_FENCE_BEFORE() asm volatile("tcgen05.fence::before_thread_sync;" ::: "memory")
#define TCG_FENCE_AFTER()  asm volatile("tcgen05.fence::after_thread_sync;" ::: "memory")
#define TCG_WAIT_LD()     asm volatile("tcgen05.wait::ld.sync.aligned;" ::: "memory")
#define TCG_WAIT_ST()     asm volatile("tcgen05.wait::st.sync.aligned;" ::: "memory")
#define FENCE_ASYNC()     asm volatile("fence.proxy.async.shared::cta;" ::: "memory")
#define MBAR_INIT(m, c)   asm volatile("mbarrier.init.shared.b64 [%0], %1;" :: "r"(m), "r"(c) : "memory")
#define MBAR_INVAL(m)     asm volatile("mbarrier.inval.shared.b64 [%0];" :: "r"(m) : "memory")

__device__ __forceinline__ void mbar_wait(uint32_t m, uint32_t parity) {
    asm volatile(
        "{\n\t.reg .pred P1;\n\t"
        "W_%=:\n\t"
        "mbarrier.try_wait.parity.acquire.cta.shared::cta.b64 P1, [%0], %1, 0x989680;\n\t"
        "@P1 bra.uni D_%=;\n\t"
        "bra.uni W_%=;\n\t"
        "D_%=:\n\t}"
        :: "r"(m), "r"(parity) : "memory");
}

#define TCG_LD_X32(r, addr) \
    asm volatile( \
        "tcgen05.ld.sync.aligned.32x32b.x32.b32 " \
        "{%0, %1, %2, %3, %4, %5, %6, %7, " \
        " %8, %9, %10, %11, %12, %13, %14, %15, " \
        " %16, %17, %18, %19, %20, %21, %22, %23, " \
        " %24, %25, %26, %27, %28, %29, %30, %31}, [%32];" \
        : "=r"((r)[0]),  "=r"((r)[1]),  "=r"((r)[2]),  "=r"((r)[3]), \
          "=r"((r)[4]),  "=r"((r)[5]),  "=r"((r)[6]),  "=r"((r)[7]), \
          "=r"((r)[8]),  "=r"((r)[9]),  "=r"((r)[10]), "=r"((r)[11]), \
          "=r"((r)[12]), "=r"((r)[13]), "=r"((r)[14]), "=r"((r)[15]), \
          "=r"((r)[16]), "=r"((r)[17]), "=r"((r)[18]), "=r"((r)[19]), \
          "=r"((r)[20]), "=r"((r)[21]), "=r"((r)[22]), "=r"((r)[23]), \
          "=r"((r)[24]), "=r"((r)[25]), "=r"((r)[26]), "=r"((r)[27]), \
          "=r"((r)[28]), "=r"((r)[29]), "=r"((r)[30]), "=r"((r)[31]) \
        : "r"(addr))

#define TCG_ST_X32(addr, r) \
    asm volatile( \
        "tcgen05.st.sync.aligned.32x32b.x32.b32 [%0], " \
        "{%1, %2, %3, %4, %5, %6, %7, %8, " \
        " %9, %10, %11, %12, %13, %14, %15, %16, " \
        " %17, %18, %19, %20, %21, %22, %23, %24, " \
        " %25, %26, %27, %28, %29, %30, %31, %32};" \
        :: "r"(addr), \
           "r"((r)[0]),  "r"((r)[1]),  "r"((r)[2]),  "r"((r)[3]), \
           "r"((r)[4]),  "r"((r)[5]),  "r"((r)[6]),  "r"((r)[7]), \
           "r"((r)[8]),  "r"((r)[9]),  "r"((r)[10]), "r"((r)[11]), \
           "r"((r)[12]), "r"((r)[13]), "r"((r)[14]), "r"((r)[15]), \
           "r"((r)[16]), "r"((r)[17]), "r"((r)[18]), "r"((r)[19]), \
           "r"((r)[20]), "r"((r)[21]), "r"((r)[22]), "r"((r)[23]), \
           "r"((r)[24]), "r"((r)[25]), "r"((r)[26]), "r"((r)[27]), \
           "r"((r)[28]), "r"((r)[29]), "r"((r)[30]), "r"((r)[31]) \
        : "memory")

static constexpr uint64_t DESC_BASE_SW128 =
    (uint64_t(2)  << 61) | (uint64_t(1) << 46) |
    (uint64_t(64) << 32) | (uint64_t(1) << 16);
#define MK_DESC(a) (DESC_BASE_SW128 | ((uint64_t)((a) >> 4) & 0x3FFF))

__device__ __forceinline__ void mma_f16_ss(uint32_t d_tmem, uint64_t a_desc,
                                           uint64_t b_desc, uint32_t idesc,
                                           bool accum) {
#if HAS_TCGEN05
    uint32_t en = accum ? 1u : 0u;
    asm volatile(
        "{\n\t.reg .pred p;\n\tsetp.ne.u32 p, %5, 0;\n\t"
        "tcgen05.mma.cta_group::1.kind::f16 [%0], %1, %2, %3, {%4, %4, %4, %4}, p;\n\t}"
        :: "r"(d_tmem), "l"(a_desc), "l"(b_desc), "r"(idesc), "r"(0u), "r"(en)
        : "memory");
#endif
}

__device__ __forceinline__ void mma_f16_ts(uint32_t d_tmem, uint32_t a_tmem,
                                           uint64_t b_desc, uint32_t idesc,
                                           bool accum) {
#if HAS_TCGEN05
    uint32_t en = accum ? 1u : 0u;
    asm volatile(
        "{\n\t.reg .pred p;\n\tsetp.ne.u32 p, %5, 0;\n\t"
        "tcgen05.mma.cta_group::1.kind::f16 [%0], [%1], %2, %3, {%4, %4, %4, %4}, p;\n\t}"
        :: "r"(d_tmem), "r"(a_tmem), "l"(b_desc), "r"(idesc), "r"(0u), "r"(en)
        : "memory");
#endif
}

#define IDESC_128 0x8200490u   // M=128, N=128, bf16->fp32

__device__ __forceinline__ uint32_t blk_addr(int row, int c16, int rows8) {
    uint32_t byte = (uint32_t)((((row >> 3) + (c16 >> 3) * rows8) << 10)
                   + ((row & 7) << 7) + ((c16 & 7) << 4));
    return byte ^ ((byte >> 3) & 0x70);
}

__device__ __forceinline__ void split2(float a0, float a1, uint32_t& h, uint32_t& l) {
    asm("cvt.rn.bf16x2.f32 %0, %1, %2;" : "=r"(h) : "f"(a1), "f"(a0));
    float f0 = __uint_as_float(h << 16);
    float f1 = __uint_as_float(h & 0xFFFF0000u);
    float r0 = a0 - f0, r1 = a1 - f1;
    asm("cvt.rn.bf16x2.f32 %0, %1, %2;" : "=r"(l) : "f"(r1), "f"(r0));
}

// ---------------- X transpose+split (z<8, float4 loads) + W split (z==8) ----
__global__ void __launch_bounds__(256) prep_kernel(
    const float* __restrict__ x_inner, const float* __restrict__ x_outer,
    const float* __restrict__ Wq, const float* __restrict__ Wk,
    const float* __restrict__ Wv) {
    int z = blockIdx.z;
    int tid = threadIdx.x;
    if (z == 8) {
        int linear = blockIdx.y * 32 + blockIdx.x;
        if (linear >= 192) { GRID_TRIGGER(); return; }
        int which = linear >> 6;
        const float* W = (which == 0) ? Wq : (which == 1) ? Wk : Wv;
        int idx = ((linear & 63) * 256 + tid) * 2;
        float a0 = W[idx], a1 = W[idx + 1];
        uint32_t h, l;
        split2(a0, a1, h, l);
        *(uint32_t*)(g_Whi + which * D_ * C_ + idx) = h;
        *(uint32_t*)(g_Wlo + which * D_ * C_ + idx) = l;
        GRID_TRIGGER();
        return;
    }
    int input = z >> 2, cb = z & 3;
    const float* X = input ? x_outer : x_inner;
    __nv_bfloat16* Ohi = input ? g_Xto_hi : g_Xti_hi;
    __nv_bfloat16* Olo = input ? g_Xto_lo : g_Xti_lo;
    int b = blockIdx.y;
    int l0 = blockIdx.x * 64, c0 = cb * 64;
    __shared__ float t[64][65];
    const float* Xb = X + ((size_t)b * C_ + c0) * L_ + l0;
    {
        float4 v[4];
#pragma unroll
        for (int p = 0; p < 4; ++p) {
            int e = tid + p * 256;
            int c = e >> 4, l4 = (e & 15) * 4;
            v[p] = *(const float4*)&Xb[(size_t)c * L_ + l4];
        }
#pragma unroll
        for (int p = 0; p < 4; ++p) {
            int e = tid + p * 256;
            int c = e >> 4, l4 = (e & 15) * 4;
            t[c][l4]     = v[p].x;
            t[c][l4 + 1] = v[p].y;
            t[c][l4 + 2] = v[p].z;
            t[c][l4 + 3] = v[p].w;
        }
    }
    __syncthreads();
    __nv_bfloat16* oh = Ohi + ((size_t)b * L_ + l0) * C_ + c0;
    __nv_bfloat16* ol = Olo + ((size_t)b * L_ + l0) * C_ + c0;
    for (int e = tid; e < 2048; e += 256) {
        int l = e >> 5, cp = e & 31;
        uint32_t h, lo;
        split2(t[cp * 2][l], t[cp * 2 + 1][l], h, lo);
        *(uint32_t*)(oh + (size_t)l * C_ + cp * 2) = h;
        *(uint32_t*)(ol + (size_t)l * C_ + cp * 2) = lo;
    }
    GRID_TRIGGER();
}

// ---------------- tensor-core projection (R15, + PDL) ----------------
#define POFF_BIAS 128
#define POFF_A    1024
#define POFF_AL   (POFF_A  + 32768)
#define POFF_WH   (POFF_AL + 32768)
#define POFF_WL   (POFF_WH + 32768)
#define PROJ_SMEM (POFF_WL + 32768)
#define VSH_STRIDE 68

__global__ void __launch_bounds__(256, 1) proj_tc_kernel(
    const float* __restrict__ bq, const float* __restrict__ bk,
    const float* __restrict__ bv) {
#if HAS_TCGEN05
    extern __shared__ char smem[];
    uint32_t sb = smem_u32(smem);
    int tid = threadIdx.x;
    int w = tid >> 5;
    int lane = tid & 31;
    int sub = w & 3;
    int ch = w >> 2;
    int row = sub * 32 + lane;
    int which = blockIdx.z;
    int b = blockIdx.y;
    int l0 = blockIdx.x * 128;

    // prologue (overlaps prep tail under PDL): alloc, mbar, bias
    const float* bias = (which == 0) ? bq : (which == 1) ? bk : bv;
    float* biasf = (float*)(smem + POFF_BIAS);
    if (tid < 128) biasf[tid] = bias[tid];

    if (w == 0) {
        TCG_ALLOC(sb + 0, 128);
        if (elect_one()) MBAR_INIT(sb + 8, 1);
    }
    __syncthreads();
    uint32_t tbase;
    asm volatile("ld.shared.b32 %0, [%1];" : "=r"(tbase) : "r"(sb + 0));

    const __nv_bfloat16 *Ah, *Al, *Bh, *Bl;
    if (which == 2) {
        Ah = g_Whi + 2 * D_ * C_;
        Al = g_Wlo + 2 * D_ * C_;
        Bh = g_Xto_hi + ((size_t)b * L_ + l0) * C_;
        Bl = g_Xto_lo + ((size_t)b * L_ + l0) * C_;
    } else {
        Ah = ((which == 0) ? g_Xti_hi : g_Xto_hi) + ((size_t)b * L_ + l0) * C_;
        Al = ((which == 0) ? g_Xti_lo : g_Xto_lo) + ((size_t)b * L_ + l0) * C_;
        Bh = g_Whi + (size_t)which * D_ * C_;
        Bl = g_Wlo + (size_t)which * D_ * C_;
    }

    const int IA[3] = {0, 0, 1}, IB[3] = {0, 1, 0};

    int rr[8], cc[8];
    uint32_t aa[8];
#pragma unroll
    for (int p = 0; p < 8; ++p) {
        int i = tid + p * 256;
        rr[p] = i >> 4; cc[p] = i & 15;
        aa[p] = blk_addr(rr[p], cc[p], 16);
    }

    GRID_DEP_SYNC();   // prep outputs must be visible from here on

    // ---- half 0: load + MMA ----
#pragma unroll
    for (int p = 0; p < 8; ++p) {
        size_t go = (size_t)rr[p] * C_ + cc[p] * 8;
        *(uint4*)(smem + POFF_A  + aa[p]) = *(const uint4*)(Ah + go);
        *(uint4*)(smem + POFF_AL + aa[p]) = *(const uint4*)(Al + go);
        *(uint4*)(smem + POFF_WH + aa[p]) = *(const uint4*)(Bh + go);
        *(uint4*)(smem + POFF_WL + aa[p]) = *(const uint4*)(Bl + go);
    }
    FENCE_ASYNC();
    __syncthreads();
    if (w == 0) {
        uint64_t ad[2] = {MK_DESC(sb + POFF_A),  MK_DESC(sb + POFF_AL)};
        uint64_t bd[2] = {MK_DESC(sb + POFF_WH), MK_DESC(sb + POFF_WL)};
        if (elect_one()) {
            bool acc = false;
#pragma unroll
            for (int p3 = 0; p3 < 3; ++p3)
#pragma unroll
                for (int ks = 0; ks < 8; ++ks) {
                    uint64_t off = (uint64_t)((ks & 3) * 2 + (ks >> 2) * 1024);
                    mma_f16_ss(tbase, ad[IA[p3]] + off, bd[IB[p3]] + off, IDESC_128, acc);
                    acc = true;
                }
            TCG_COMMIT(sb + 8);
        }
    }

    uint4 pah[8], pal[8];
#pragma unroll
    for (int p = 0; p < 8; ++p) {
        size_t go = (size_t)rr[p] * C_ + 128 + cc[p] * 8;
        pah[p] = *(const uint4*)(Ah + go);
        pal[p] = *(const uint4*)(Al + go);
    }

    mbar_wait(sb + 8, 0);
    TCG_FENCE_AFTER();

    {
        uint4 pbh[8], pbl[8];
#pragma unroll
        for (int p = 0; p < 8; ++p) {
            size_t go = (size_t)rr[p] * C_ + 128 + cc[p] * 8;
            pbh[p] = *(const uint4*)(Bh + go);
            pbl[p] = *(const uint4*)(Bl + go);
        }
#pragma unroll
        for (int p = 0; p < 8; ++p) {
            *(uint4*)(smem + POFF_A  + aa[p]) = pah[p];
            *(uint4*)(smem + POFF_AL + aa[p]) = pal[p];
        }
#pragma unroll
        for (int p = 0; p < 8; ++p) {
            *(uint4*)(smem + POFF_WH + aa[p]) = pbh[p];
            *(uint4*)(smem + POFF_WL + aa[p]) = pbl[p];
        }
    }
    FENCE_ASYNC();
    __syncthreads();
    if (w == 0) {
        uint64_t ad[2] = {MK_DESC(sb + POFF_A),  MK_DESC(sb + POFF_AL)};
        uint64_t bd[2] = {MK_DESC(sb + POFF_WH), MK_DESC(sb + POFF_WL)};
        if (elect_one()) {
            bool acc = true;
#pragma unroll
            for (int p3 = 0; p3 < 3; ++p3)
#pragma unroll
                for (int ks = 0; ks < 8; ++ks) {
                    uint64_t off = (uint64_t)((ks & 3) * 2 + (ks >> 2) * 1024);
                    mma_f16_ss(tbase, ad[IA[p3]] + off, bd[IB[p3]] + off, IDESC_128, acc);
                }
            TCG_COMMIT(sb + 8);
        }
    }

    mbar_wait(sb + 8, 1);
    TCG_FENCE_AFTER();
    if (which != 2) {
        // Q prescaled by QK_SCALE*log2e so flash softmax uses bare ex2
        float scale = (which == 0) ? (QK_SCALE * LOG2E) : 1.0f;
        __nv_bfloat16* Ohi = (which == 0) ? g_Qhi : g_Khi;
        __nv_bfloat16* Olo = (which == 0) ? g_Qlo : g_Klo;
        size_t obase = ((size_t)(b * L_ + l0 + row)) * D_;
#pragma unroll
        for (int hc = 0; hc < 2; ++hc) {
            uint32_t tr[32];
            TCG_LD_X32(tr, tbase + ch * 64 + hc * 32);
            TCG_WAIT_LD();
            int d0 = ch * 64 + hc * 32;
#pragma unroll
            for (int j = 0; j < 32; j += 2) {
                float a0 = (__uint_as_float(tr[j])     + biasf[d0 + j])     * scale;
                float a1 = (__uint_as_float(tr[j + 1]) + biasf[d0 + j + 1]) * scale;
                uint32_t h, l;
                split2(a0, a1, h, l);
                *(uint32_t*)(Ohi + obase + d0 + j) = h;
                *(uint32_t*)(Olo + obase + d0 + j) = l;
            }
        }
        TCG_FENCE_BEFORE();
        GRID_TRIGGER();
    } else {
        uint32_t* ShH = (uint32_t*)(smem + POFF_A);
        uint32_t* ShL = ShH + 128 * VSH_STRIDE;
        float bv_r = biasf[row];
#pragma unroll
        for (int hc = 0; hc < 2; ++hc) {
            uint32_t tr[32];
            TCG_LD_X32(tr, tbase + ch * 64 + hc * 32);
            TCG_WAIT_LD();
#pragma unroll
            for (int j = 0; j < 32; j += 2) {
                float a0 = __uint_as_float(tr[j])     + bv_r;
                float a1 = __uint_as_float(tr[j + 1]) + bv_r;
                uint32_t h, l;
                split2(a0, a1, h, l);
                int col = ch * 32 + hc * 16 + (j >> 1);
                ShH[row * VSH_STRIDE + col] = h;
                ShL[row * VSH_STRIDE + col] = l;
            }
        }
        TCG_FENCE_BEFORE();
        __syncthreads();
        size_t vbase = ((size_t)b * D_) * L_ + l0;
#pragma unroll
        for (int p = 0; p < 8; ++p) {
            int e = tid + p * 256;
            int r = e >> 4, q = e & 15;
            uint4 vh = *(uint4*)&ShH[r * VSH_STRIDE + q * 4];
            uint4 vl = *(uint4*)&ShL[r * VSH_STRIDE + q * 4];
            *(uint4*)(g_Vthi + vbase + (size_t)r * L_ + q * 8) = vh;
            *(uint4*)(g_Vtlo + vbase + (size_t)r * L_ + q * 8) = vl;
        }
        GRID_TRIGGER();
    }

    __syncthreads();
    if (w == 0) {
        if (elect_one()) MBAR_INVAL(sb + 8);
        TCG_RELINQ();
        TCG_DEALLOC(tbase, 128);
    }
#endif
}

// ---------------- tensor-core flash attention (R10 + ex2 + PDL) ------------
#define OFF_RED   128
#define OFF_QHI   2048
#define OFF_QLO   (OFF_QHI + 32768)
#define OFF_KHI   (OFF_QLO + 32768)
#define OFF_KLO   (OFF_KHI + 32768)
#define OFF_VHI   (OFF_KLO + 32768)
#define OFF_VLO   (OFF_VHI + 32768)
#define FLASH_SMEM (OFF_VLO + 32768)   // 198656 bytes

#define MB_QK 8
#define MB_PV 16
#define NT 16

__global__ void __launch_bounds__(256, 1) flash_tc_kernel(float* __restrict__ Og) {
#if HAS_TCGEN05
    extern __shared__ char smem[];
    uint32_t sb = smem_u32(smem);
    int tid = threadIdx.x;
    int w = tid >> 5;
    int lane = tid & 31;
    int sub = w & 3;
    int ch = w >> 2;
    int row = sub * 32 + lane;
    int b = blockIdx.y;
    int q0 = blockIdx.x * 128;

    // prologue (overlaps proj tail under PDL)
    if (w == 0) {
        TCG_ALLOC(sb + 0, 512);
        if (elect_one()) { MBAR_INIT(sb + MB_QK, 1); MBAR_INIT(sb + MB_PV, 1); }
    }
    __syncthreads();
    uint32_t tbase;
    asm volatile("ld.shared.b32 %0, [%1];" : "=r"(tbase) : "r"(sb + 0));
    uint32_t tmem_o = tbase;
    uint32_t tmem_s[2] = {tbase + 128, tbase + 256};
    uint32_t tmem_phi = tbase + 384;
    uint32_t tmem_plo = tbase + 448;
    uint32_t wofs = (uint32_t)sub << 21;

    const int IA[3] = {0, 0, 1}, IB[3] = {0, 1, 0};
    float* redf = (float*)(smem + OFF_RED);
    const __nv_bfloat16* Kgh = g_Khi + (size_t)b * L_ * D_;
    const __nv_bfloat16* Kgl = g_Klo + (size_t)b * L_ * D_;
    size_t vtb = (size_t)b * D_ * L_;

    int rr[8], cc[8];
    uint32_t aa[8];
#pragma unroll
    for (int p = 0; p < 8; ++p) {
        int i = tid + p * 256;
        rr[p] = i >> 4; cc[p] = i & 15;
        aa[p] = blk_addr(rr[p], cc[p], 16);
    }

    GRID_DEP_SYNC();   // proj outputs must be visible from here on

    {
        size_t qoff = ((size_t)(b * L_ + q0)) * D_;
#pragma unroll
        for (int p = 0; p < 8; ++p) {
            size_t go = (size_t)rr[p] * D_ + cc[p] * 8;
            *(uint4*)(smem + OFF_QHI + aa[p]) = *(const uint4*)(g_Qhi + qoff + go);
            *(uint4*)(smem + OFF_QLO + aa[p]) = *(const uint4*)(g_Qlo + qoff + go);
            *(uint4*)(smem + OFF_KHI + aa[p]) = *(const uint4*)(Kgh + go);
            *(uint4*)(smem + OFF_KLO + aa[p]) = *(const uint4*)(Kgl + go);
            size_t vo = vtb + (size_t)rr[p] * L_ + cc[p] * 8;
            *(uint4*)(smem + OFF_VHI + aa[p]) = *(const uint4*)(g_Vthi + vo);
            *(uint4*)(smem + OFF_VLO + aa[p]) = *(const uint4*)(g_Vtlo + vo);
        }
    }
    FENCE_ASYNC();
    __syncthreads();

    if (w == 0) {
        uint64_t ad[2] = {MK_DESC(sb + OFF_QHI), MK_DESC(sb + OFF_QLO)};
        uint64_t bd[2] = {MK_DESC(sb + OFF_KHI), MK_DESC(sb + OFF_KLO)};
        if (elect_one()) {
            bool acc = false;
#pragma unroll
            for (int p3 = 0; p3 < 3; ++p3)
#pragma unroll
                for (int ks = 0; ks < 8; ++ks) {
                    uint64_t off = (uint64_t)((ks & 3) * 2 + (ks >> 2) * 1024);
                    mma_f16_ss(tmem_s[0], ad[IA[p3]] + off, bd[IB[p3]] + off, IDESC_128, acc);
                    acc = true;
                }
            TCG_COMMIT(sb + MB_QK);
        }
    }

    float l_run = 0.f;

    for (int t = 0; t < NT; ++t) {
        int buf = t & 1, nbuf = buf ^ 1;

        mbar_wait(sb + MB_QK, t & 1);
        TCG_FENCE_AFTER();

        uint4 kh[8], kl[8];
        if (t < NT - 1) {
            size_t koff = (size_t)(t + 1) * 128 * D_;
#pragma unroll
            for (int p = 0; p < 8; ++p) {
                size_t go = koff + (size_t)rr[p] * D_ + cc[p] * 8;
                kh[p] = *(const uint4*)(Kgh + go);
                kl[p] = *(const uint4*)(Kgl + go);
            }
        }

        uint32_t sr[64];
        TCG_LD_X32(sr, tmem_s[buf] + ch * 64);
        TCG_LD_X32(sr + 32, tmem_s[buf] + ch * 64 + 32);

        if (t < NT - 1) {
#pragma unroll
            for (int p = 0; p < 8; ++p) {
                *(uint4*)(smem + OFF_KHI + aa[p]) = kh[p];
                *(uint4*)(smem + OFF_KLO + aa[p]) = kl[p];
            }
        }
        TCG_WAIT_LD();
        TCG_FENCE_BEFORE();
        FENCE_ASYNC();
        __syncthreads();

        if (t < NT - 1 && w == 0) {
            uint64_t ad[2] = {MK_DESC(sb + OFF_QHI), MK_DESC(sb + OFF_QLO)};
            uint64_t bd[2] = {MK_DESC(sb + OFF_KHI), MK_DESC(sb + OFF_KLO)};
            if (elect_one()) {
                bool acc = false;
#pragma unroll
                for (int p3 = 0; p3 < 3; ++p3)
#pragma unroll
                    for (int ks = 0; ks < 8; ++ks) {
                        uint64_t off = (uint64_t)((ks & 3) * 2 + (ks >> 2) * 1024);
                        mma_f16_ss(tmem_s[nbuf], ad[IA[p3]] + off, bd[IB[p3]] + off,
                                   IDESC_128, acc);
                        acc = true;
                    }
                TCG_COMMIT(sb + MB_QK);
            }
        }

        uint4 vh[8], vl[8];
        if (t >= 1) {
            size_t vo0 = vtb + (size_t)t * 128;
#pragma unroll
            for (int p = 0; p < 8; ++p) {
                size_t go = vo0 + (size_t)rr[p] * L_ + cc[p] * 8;
                vh[p] = *(const uint4*)(g_Vthi + go);
                vl[p] = *(const uint4*)(g_Vtlo + go);
            }
        }

        // exp2 (S was pre-scaled by log2e via Q) + hi/lo split
        float lsum = 0.f;
        uint32_t hw[32], lw[32];
#pragma unroll
        for (int u = 0; u < 32; ++u) {
            float a0, a1;
            asm("ex2.approx.ftz.f32 %0, %1;" : "=f"(a0) : "f"(__uint_as_float(sr[u * 2])));
            asm("ex2.approx.ftz.f32 %0, %1;" : "=f"(a1) : "f"(__uint_as_float(sr[u * 2 + 1])));
            lsum += a0 + a1;
            split2(a0, a1, hw[u], lw[u]);
        }
        redf[ch * 128 + row] = lsum;

        if (t >= 1) { mbar_wait(sb + MB_PV, (t - 1) & 1); TCG_FENCE_AFTER(); }

        TCG_ST_X32(tmem_phi + ch * 32 + wofs, hw);
        TCG_ST_X32(tmem_plo + ch * 32 + wofs, lw);
        TCG_WAIT_ST();
        TCG_FENCE_BEFORE();

        if (t >= 1) {
#pragma unroll
            for (int p = 0; p < 8; ++p) {
                *(uint4*)(smem + OFF_VHI + aa[p]) = vh[p];
                *(uint4*)(smem + OFF_VLO + aa[p]) = vl[p];
            }
        }
        FENCE_ASYNC();
        __syncthreads();
        l_run += redf[row] + redf[128 + row];

        if (w == 0 && elect_one()) {
            TCG_FENCE_AFTER();
            uint32_t pa[2] = {tmem_phi, tmem_plo};
            uint64_t vd[2] = {MK_DESC(sb + OFF_VHI), MK_DESC(sb + OFF_VLO)};
            bool acc = (t > 0);
#pragma unroll
            for (int p3 = 0; p3 < 3; ++p3)
#pragma unroll
                for (int ks = 0; ks < 8; ++ks) {
                    uint64_t boff = (uint64_t)((ks & 3) * 2 + (ks >> 2) * 1024);
                    mma_f16_ts(tmem_o, pa[IA[p3]] + ks * 8, vd[IB[p3]] + boff,
                               IDESC_128, acc);
                    acc = true;
                }
            TCG_COMMIT(sb + MB_PV);
        }
    }

    mbar_wait(sb + MB_PV, (NT - 1) & 1);
    TCG_FENCE_AFTER();
    {
        float inv = 1.0f / l_run;
        float* Ob = Og + ((size_t)(b * L_ + q0 + row)) * D_ + ch * 64;
        uint32_t tr[32];
        TCG_LD_X32(tr, tmem_o + ch * 64);
        TCG_WAIT_LD();
#pragma unroll
        for (int j = 0; j < 32; j += 4) {
            float4 v;
            v.x = __uint_as_float(tr[j])     * inv;
            v.y = __uint_as_float(tr[j + 1]) * inv;
            v.z = __uint_as_float(tr[j + 2]) * inv;
            v.w = __uint_as_float(tr[j + 3]) * inv;
            *(float4*)&Ob[j] = v;
        }
        TCG_LD_X32(tr, tmem_o + ch * 64 + 32);
        TCG_WAIT_LD();
#pragma unroll
        for (int j = 0; j < 32; j += 4) {
            float4 v;
            v.x = __uint_as_float(tr[j])     * inv;
            v.y = __uint_as_float(tr[j + 1]) * inv;
            v.z = __uint_as_float(tr[j + 2]) * inv;
            v.w = __uint_as_float(tr[j + 3]) * inv;
            *(float4*)&Ob[32 + j] = v;
        }
        TCG_FENCE_BEFORE();
    }

    __syncthreads();
    if (w == 0) {
        if (elect_one()) { MBAR_INVAL(sb + MB_QK); MBAR_INVAL(sb + MB_PV); }
        TCG_RELINQ();
        TCG_DEALLOC(tbase, 512);
    }
#endif  // HAS_TCGEN05
}

extern "C" void kernel_launch(void* const* d_in, const int* in_sizes, int n_in,
                              void* d_out, int out_size) {
    const float* x_inner = (const float*)d_in[0];
    const float* x_outer = (const float*)d_in[1];
    const float* Wq = (const float*)d_in[2];
    const float* bq = (const float*)d_in[3];
    const float* Wk = (const float*)d_in[4];
    const float* bk = (const float*)d_in[5];
    const float* Wv = (const float*)d_in[6];
    const float* bv = (const float*)d_in[7];
    float* out = (float*)d_out;

    cudaFuncSetAttribute(proj_tc_kernel,
                         cudaFuncAttributeMaxDynamicSharedMemorySize, PROJ_SMEM);
    cudaFuncSetAttribute(flash_tc_kernel,
                         cudaFuncAttributeMaxDynamicSharedMemorySize, FLASH_SMEM);

    prep_kernel<<<dim3(L_ / 64, B_, 9), 256>>>(x_inner, x_outer, Wq, Wk, Wv);

    cudaLaunchAttribute pdl[1];
    pdl[0].id = cudaLaunchAttributeProgrammaticStreamSerialization;
    pdl[0].val.programmaticStreamSerializationAllowed = 1;

    {
        cudaLaunchConfig_t cfg = {};
        cfg.gridDim = dim3(L_ / 128, B_, 3);
        cfg.blockDim = dim3(256, 1, 1);
        cfg.dynamicSmemBytes = PROJ_SMEM;
        cfg.stream = 0;
        cfg.attrs = pdl;
        cfg.numAttrs = 1;
        cudaLaunchKernelEx(&cfg, proj_tc_kernel, bq, bk, bv);
    }
    {
        cudaLaunchConfig_t cfg = {};
        cfg.gridDim = dim3(L_ / 128, B_, 1);
        cfg.blockDim = dim3(256, 1, 1);
        cfg.dynamicSmemBytes = FLASH_SMEM;
        cfg.stream = 0;
        cfg.attrs = pdl;
        cfg.numAttrs = 1;
        cudaLaunchKernelEx(&cfg, flash_tc_kernel, out);
    }
}

// round 17
// speedup vs baseline: 1.5893x; 1.0387x over previous
#include <cuda_runtime.h>
#include <cuda_bf16.h>
#include <math_constants.h>
#include <cstdint>

#define B_  8
#define C_  256
#define L_  2048
#define D_  128
#define QK_SCALE 0.08838834764831845f  // 1/sqrt(128)
#define LOG2E    1.4426950408889634f

#if defined(__CUDA_ARCH_FEAT_SM103_ALL) || defined(__CUDA_ARCH_FEAT_SM101_ALL) || \
    defined(__CUDA_ARCH_FEAT_SM100_ALL) || \
    (defined(__CUDA_ARCH_SPECIFIC__) && (__CUDA_ARCH_SPECIFIC__ >= 1000))
#define HAS_TCGEN05 1
#else
#define HAS_TCGEN05 0
#endif

#if defined(__CUDA_ARCH__) && (__CUDA_ARCH__ >= 900)
#define GRID_DEP_SYNC()  cudaGridDependencySynchronize()
#define GRID_TRIGGER()   cudaTriggerProgrammaticLaunchCompletion()
#else
#define GRID_DEP_SYNC()
#define GRID_TRIGGER()
#endif

// ---------------- global scratch ----------------
__device__ __nv_bfloat16 g_Qhi[B_*L_*D_], g_Qlo[B_*L_*D_];
__device__ __nv_bfloat16 g_Khi[B_*L_*D_], g_Klo[B_*L_*D_];
__device__ __nv_bfloat16 g_Vthi[B_*D_*L_], g_Vtlo[B_*D_*L_];  // [B][D][L]
__device__ __nv_bfloat16 g_Whi[3*D_*C_], g_Wlo[3*D_*C_];

// ---------------- PTX helpers ----------------
__device__ __forceinline__ uint32_t smem_u32(const void* p) {
    uint32_t a;
    asm("{ .reg .u64 t; cvta.to.shared.u64 t, %1; cvt.u32.u64 %0, t; }"
        : "=r"(a) : "l"(p));
    return a;
}
__device__ __forceinline__ uint32_t elect_one() {
    uint32_t p;
    asm volatile("{\n\t.reg .pred p;\n\telect.sync _|p, 0xFFFFFFFF;\n\t"
                 "selp.b32 %0, 1, 0, p;\n\t}" : "=r"(p));
    return p;
}
#define TCG_ALLOC(sm, n)  asm volatile("tcgen05.alloc.cta_group::1.sync.aligned.shared::cta.b32 [%0], %1;" :: "r"(sm), "r"(n) : "memory")
#define TCG_DEALLOC(t, n) asm volatile("tcgen05.dealloc.cta_group::1.sync.aligned.b32 %0, %1;" :: "r"(t), "r"(n))
#define TCG_RELINQ()      asm volatile("tcgen05.relinquish_alloc_permit.cta_group::1.sync.aligned;")
#define TCG_COMMIT(m)     asm volatile("tcgen05.commit.cta_group::1.mbarrier::arrive::one.shared::cluster.b64 [%0];" :: "r"(m) : "memory")
#define TCG_FENCE_BEFORE() asm volatile("tcgen05.fence::before_thread_sync;" ::: "memory")
#define TCG_FENCE_AFTER()  asm volatile("tcgen05.fence::after_thread_sync;" ::: "memory")
#define TCG_WAIT_LD()     asm volatile("tcgen05.wait::ld.sync.aligned;" ::: "memory")
#define TCG_WAIT_ST()     asm volatile("tcgen05.wait::st.sync.aligned;" ::: "memory")
#define FENCE_ASYNC()     asm volatile("fence.proxy.async.shared::cta;" ::: "memory")
#define MBAR_INIT(m, c)   asm volatile("mbarrier.init.shared.b64 [%0], %1;" :: "r"(m), "r"(c) : "memory")
#define MBAR_INVAL(m)     asm volatile("mbarrier.inval.shared.b64 [%0];" :: "r"(m) : "memory")

__device__ __forceinline__ void mbar_wait(uint32_t m, uint32_t parity) {
    asm volatile(
        "{\n\t.reg .pred P1;\n\t"
        "W_%=:\n\t"
        "mbarrier.try_wait.parity.acquire.cta.shared::cta.b64 P1, [%0], %1, 0x989680;\n\t"
        "@P1 bra.uni D_%=;\n\t"
        "bra.uni W_%=;\n\t"
        "D_%=:\n\t}"
        :: "r"(m), "r"(parity) : "memory");
}

#define TCG_LD_X32(r, addr) \
    asm volatile( \
        "tcgen05.ld.sync.aligned.32x32b.x32.b32 " \
        "{%0, %1, %2, %3, %4, %5, %6, %7, " \
        " %8, %9, %10, %11, %12, %13, %14, %15, " \
        " %16, %17, %18, %19, %20, %21, %22, %23, " \
        " %24, %25, %26, %27, %28, %29, %30, %31}, [%32];" \
        : "=r"((r)[0]),  "=r"((r)[1]),  "=r"((r)[2]),  "=r"((r)[3]), \
          "=r"((r)[4]),  "=r"((r)[5]),  "=r"((r)[6]),  "=r"((r)[7]), \
          "=r"((r)[8]),  "=r"((r)[9]),  "=r"((r)[10]), "=r"((r)[11]), \
          "=r"((r)[12]), "=r"((r)[13]), "=r"((r)[14]), "=r"((r)[15]), \
          "=r"((r)[16]), "=r"((r)[17]), "=r"((r)[18]), "=r"((r)[19]), \
          "=r"((r)[20]), "=r"((r)[21]), "=r"((r)[22]), "=r"((r)[23]), \
          "=r"((r)[24]), "=r"((r)[25]), "=r"((r)[26]), "=r"((r)[27]), \
          "=r"((r)[28]), "=r"((r)[29]), "=r"((r)[30]), "=r"((r)[31]) \
        : "r"(addr))

#define TCG_ST_X32(addr, r) \
    asm volatile( \
        "tcgen05.st.sync.aligned.32x32b.x32.b32 [%0], " \
        "{%1, %2, %3, %4, %5, %6, %7, %8, " \
        " %9, %10, %11, %12, %13, %14, %15, %16, " \
        " %17, %18, %19, %20, %21, %22, %23, %24, " \
        " %25, %26, %27, %28, %29, %30, %31, %32};" \
        :: "r"(addr), \
           "r"((r)[0]),  "r"((r)[1]),  "r"((r)[2]),  "r"((r)[3]), \
           "r"((r)[4]),  "r"((r)[5]),  "r"((r)[6]),  "r"((r)[7]), \
           "r"((r)[8]),  "r"((r)[9]),  "r"((r)[10]), "r"((r)[11]), \
           "r"((r)[12]), "r"((r)[13]), "r"((r)[14]), "r"((r)[15]), \
           "r"((r)[16]), "r"((r)[17]), "r"((r)[18]), "r"((r)[19]), \
           "r"((r)[20]), "r"((r)[21]), "r"((r)[22]), "r"((r)[23]), \
           "r"((r)[24]), "r"((r)[25]), "r"((r)[26]), "r"((r)[27]), \
           "r"((r)[28]), "r"((r)[29]), "r"((r)[30]), "r"((r)[31]) \
        : "memory")

static constexpr uint64_t DESC_BASE_SW128 =
    (uint64_t(2)  << 61) | (uint64_t(1) << 46) |
    (uint64_t(64) << 32) | (uint64_t(1) << 16);
#define MK_DESC(a) (DESC_BASE_SW128 | ((uint64_t)((a) >> 4) & 0x3FFF))

__device__ __forceinline__ void mma_f16_ss(uint32_t d_tmem, uint64_t a_desc,
                                           uint64_t b_desc, uint32_t idesc,
                                           bool accum) {
#if HAS_TCGEN05
    uint32_t en = accum ? 1u : 0u;
    asm volatile(
        "{\n\t.reg .pred p;\n\tsetp.ne.u32 p, %5, 0;\n\t"
        "tcgen05.mma.cta_group::1.kind::f16 [%0], %1, %2, %3, {%4, %4, %4, %4}, p;\n\t}"
        :: "r"(d_tmem), "l"(a_desc), "l"(b_desc), "r"(idesc), "r"(0u), "r"(en)
        : "memory");
#endif
}

__device__ __forceinline__ void mma_f16_ts(uint32_t d_tmem, uint32_t a_tmem,
                                           uint64_t b_desc, uint32_t idesc,
                                           bool accum) {
#if HAS_TCGEN05
    uint32_t en = accum ? 1u : 0u;
    asm volatile(
        "{\n\t.reg .pred p;\n\tsetp.ne.u32 p, %5, 0;\n\t"
        "tcgen05.mma.cta_group::1.kind::f16 [%0], [%1], %2, %3, {%4, %4, %4, %4}, p;\n\t}"
        :: "r"(d_tmem), "r"(a_tmem), "l"(b_desc), "r"(idesc), "r"(0u), "r"(en)
        : "memory");
#endif
}

#define IDESC_128 0x8200490u   // M=128, N=128, bf16->fp32

__device__ __forceinline__ uint32_t blk_addr(int row, int c16, int rows8) {
    uint32_t byte = (uint32_t)((((row >> 3) + (c16 >> 3) * rows8) << 10)
                   + ((row & 7) << 7) + ((c16 & 7) << 4));
    return byte ^ ((byte >> 3) & 0x70);
}

__device__ __forceinline__ void split2(float a0, float a1, uint32_t& h, uint32_t& l) {
    asm("cvt.rn.bf16x2.f32 %0, %1, %2;" : "=r"(h) : "f"(a1), "f"(a0));
    float f0 = __uint_as_float(h << 16);
    float f1 = __uint_as_float(h & 0xFFFF0000u);
    float r0 = a0 - f0, r1 = a1 - f1;
    asm("cvt.rn.bf16x2.f32 %0, %1, %2;" : "=r"(l) : "f"(r1), "f"(r0));
}

// ---------------- W split only ----------------
__global__ void __launch_bounds__(256) prep_kernel(
    const float* __restrict__ Wq, const float* __restrict__ Wk,
    const float* __restrict__ Wv) {
    int which = blockIdx.y;
    const float* W = (which == 0) ? Wq : (which == 1) ? Wk : Wv;
    int idx = (blockIdx.x * 256 + threadIdx.x) * 2;
    float a0 = W[idx], a1 = W[idx + 1];
    uint32_t h, l;
    split2(a0, a1, h, l);
    *(uint32_t*)(g_Whi + which * D_ * C_ + idx) = h;
    *(uint32_t*)(g_Wlo + which * D_ * C_ + idx) = l;
    GRID_TRIGGER();
}

// ---------------- tensor-core projection with fused X transpose+split -------
// which 0 (Q): A = Xi^T tile, B = Wq  -> out [l][d]
// which 1 (K): A = Xo^T tile, B = Wk  -> out [l][d]
// which 2 (V): A = Wv, B = Xo^T tile  -> out [d][l]
// X tiles are staged fp32 (coalesced along l), transposed+split in-CTA.
#define POFF_BIAS 128
#define POFF_A    1024
#define POFF_AL   (POFF_A  + 32768)
#define POFF_WH   (POFF_AL + 32768)
#define POFF_WL   (POFF_WH + 32768)
#define POFF_STG  (POFF_WL + 32768)            // 128 x 132 fp32 staging
#define PROJ_SMEM (POFF_STG + 128 * 132 * 4)   // 199680 bytes
#define VSH_STRIDE 68

__global__ void __launch_bounds__(256, 1) proj_tc_kernel(
    const float* __restrict__ x_inner, const float* __restrict__ x_outer,
    const float* __restrict__ bq, const float* __restrict__ bk,
    const float* __restrict__ bv) {
#if HAS_TCGEN05
    extern __shared__ char smem[];
    uint32_t sb = smem_u32(smem);
    int tid = threadIdx.x;
    int w = tid >> 5;
    int lane = tid & 31;
    int sub = w & 3;
    int ch = w >> 2;
    int row = sub * 32 + lane;
    int which = blockIdx.z;
    int b = blockIdx.y;
    int l0 = blockIdx.x * 128;

    // prologue (overlaps prep under PDL)
    const float* bias = (which == 0) ? bq : (which == 1) ? bk : bv;
    float* biasf = (float*)(smem + POFF_BIAS);
    if (tid < 128) biasf[tid] = bias[tid];

    if (w == 0) {
        TCG_ALLOC(sb + 0, 128);
        if (elect_one()) MBAR_INIT(sb + 8, 1);
    }
    __syncthreads();
    uint32_t tbase;
    asm volatile("ld.shared.b32 %0, [%1];" : "=r"(tbase) : "r"(sb + 0));

    const float* Xg = (which == 0) ? x_inner : x_outer;   // [b][c][l] fp32
    const float* Xb = Xg + (size_t)b * C_ * L_ + l0;
    const __nv_bfloat16* Wh = g_Whi + (size_t)which * D_ * C_;
    const __nv_bfloat16* Wl = g_Wlo + (size_t)which * D_ * C_;

    // X transposed tile goes where the MMA expects it:
    int xoff  = (which == 2) ? POFF_WH : POFF_A;
    int xoffL = (which == 2) ? POFF_WL : POFF_AL;
    int woff  = (which == 2) ? POFF_A  : POFF_WH;
    int woffL = (which == 2) ? POFF_AL : POFF_WL;

    float* stg = (float*)(smem + POFF_STG);

    // W chunk coords (row-major over [d][c-half])
    int rr[8], cc[8];
    uint32_t aa[8];
#pragma unroll
    for (int p = 0; p < 8; ++p) {
        int i = tid + p * 256;
        rr[p] = i >> 4; cc[p] = i & 15;
        aa[p] = blk_addr(rr[p], cc[p], 16);
    }
    // transpose chunk coords: lane varies row -> conflict-free stg reads
    int tr_row[8], tr_c16[8];
    uint32_t tr_aa[8];
#pragma unroll
    for (int p = 0; p < 8; ++p) {
        tr_row[p] = lane + 32 * (p >> 1);
        tr_c16[p] = w + 8 * (p & 1);
        tr_aa[p] = blk_addr(tr_row[p], tr_c16[p], 16);
    }

    const int IA[3] = {0, 0, 1}, IB[3] = {0, 1, 0};

    // ---- half 0: stage X (no dep on prep) ----
    {
        float4 xv[16];
#pragma unroll
        for (int p = 0; p < 16; ++p) {
            int e = tid + p * 256;
            int c = e >> 5, q = e & 31;
            xv[p] = *(const float4*)&Xb[(size_t)c * L_ + q * 4];
        }
#pragma unroll
        for (int p = 0; p < 16; ++p) {
            int e = tid + p * 256;
            int c = e >> 5, q = e & 31;
            *(float4*)&stg[c * 132 + q * 4] = xv[p];
        }
    }
    __syncthreads();

    // transpose+split half 0 into xoff; W half 0 (after dep sync)
    GRID_DEP_SYNC();
#pragma unroll
    for (int p = 0; p < 8; ++p) {
        float f[8];
#pragma unroll
        for (int k = 0; k < 8; ++k)
            f[k] = stg[(tr_c16[p] * 8 + k) * 132 + tr_row[p]];
        uint32_t h[4], l[4];
#pragma unroll
        for (int u = 0; u < 4; ++u) split2(f[u * 2], f[u * 2 + 1], h[u], l[u]);
        *(uint4*)(smem + xoff  + tr_aa[p]) = make_uint4(h[0], h[1], h[2], h[3]);
        *(uint4*)(smem + xoffL + tr_aa[p]) = make_uint4(l[0], l[1], l[2], l[3]);
    }
#pragma unroll
    for (int p = 0; p < 8; ++p) {
        size_t go = (size_t)rr[p] * C_ + cc[p] * 8;
        *(uint4*)(smem + woff  + aa[p]) = *(const uint4*)(Wh + go);
        *(uint4*)(smem + woffL + aa[p]) = *(const uint4*)(Wl + go);
    }
    FENCE_ASYNC();
    __syncthreads();

    // MMA half 0
    if (w == 0 && elect_one()) {
        uint64_t ad[2] = {MK_DESC(sb + POFF_A),  MK_DESC(sb + POFF_AL)};
        uint64_t bd[2] = {MK_DESC(sb + POFF_WH), MK_DESC(sb + POFF_WL)};
        bool acc = false;
#pragma unroll
        for (int p3 = 0; p3 < 3; ++p3)
#pragma unroll
            for (int ks = 0; ks < 8; ++ks) {
                uint64_t off = (uint64_t)((ks & 3) * 2 + (ks >> 2) * 1024);
                mma_f16_ss(tbase, ad[IA[p3]] + off, bd[IB[p3]] + off, IDESC_128, acc);
                acc = true;
            }
        TCG_COMMIT(sb + 8);
    }

    // ---- half 1: stage X(c 128..255) while MMA0 runs ----
    {
        float4 xv[16];
#pragma unroll
        for (int p = 0; p < 16; ++p) {
            int e = tid + p * 256;
            int c = e >> 5, q = e & 31;
            xv[p] = *(const float4*)&Xb[(size_t)(128 + c) * L_ + q * 4];
        }
        __syncthreads();   // everyone done reading half-0 staging
#pragma unroll
        for (int p = 0; p < 16; ++p) {
            int e = tid + p * 256;
            int c = e >> 5, q = e & 31;
            *(float4*)&stg[c * 132 + q * 4] = xv[p];
        }
    }
    __syncthreads();

    // transpose half 1 into registers (xoff smem still read by MMA0)
    uint32_t xh[8][4], xl[8][4];
#pragma unroll
    for (int p = 0; p < 8; ++p) {
        float f[8];
#pragma unroll
        for (int k = 0; k < 8; ++k)
            f[k] = stg[(tr_c16[p] * 8 + k) * 132 + tr_row[p]];
#pragma unroll
        for (int u = 0; u < 4; ++u) split2(f[u * 2], f[u * 2 + 1], xh[p][u], xl[p][u]);
    }

    mbar_wait(sb + 8, 0);
    TCG_FENCE_AFTER();

#pragma unroll
    for (int p = 0; p < 8; ++p) {
        *(uint4*)(smem + xoff  + tr_aa[p]) = make_uint4(xh[p][0], xh[p][1], xh[p][2], xh[p][3]);
        *(uint4*)(smem + xoffL + tr_aa[p]) = make_uint4(xl[p][0], xl[p][1], xl[p][2], xl[p][3]);
    }
#pragma unroll
    for (int p = 0; p < 8; ++p) {
        size_t go = (size_t)rr[p] * C_ + 128 + cc[p] * 8;
        *(uint4*)(smem + woff  + aa[p]) = *(const uint4*)(Wh + go);
        *(uint4*)(smem + woffL + aa[p]) = *(const uint4*)(Wl + go);
    }
    FENCE_ASYNC();
    __syncthreads();

    if (w == 0 && elect_one()) {
        uint64_t ad[2] = {MK_DESC(sb + POFF_A),  MK_DESC(sb + POFF_AL)};
        uint64_t bd[2] = {MK_DESC(sb + POFF_WH), MK_DESC(sb + POFF_WL)};
        bool acc = true;
#pragma unroll
        for (int p3 = 0; p3 < 3; ++p3)
#pragma unroll
            for (int ks = 0; ks < 8; ++ks) {
                uint64_t off = (uint64_t)((ks & 3) * 2 + (ks >> 2) * 1024);
                mma_f16_ss(tbase, ad[IA[p3]] + off, bd[IB[p3]] + off, IDESC_128, acc);
            }
        TCG_COMMIT(sb + 8);
    }

    // ---- epilogue ----
    mbar_wait(sb + 8, 1);
    TCG_FENCE_AFTER();
    if (which != 2) {
        float scale = (which == 0) ? (QK_SCALE * LOG2E) : 1.0f;
        __nv_bfloat16* Ohi = (which == 0) ? g_Qhi : g_Khi;
        __nv_bfloat16* Olo = (which == 0) ? g_Qlo : g_Klo;
        size_t obase = ((size_t)(b * L_ + l0 + row)) * D_;
#pragma unroll
        for (int hc = 0; hc < 2; ++hc) {
            uint32_t tr[32];
            TCG_LD_X32(tr, tbase + ch * 64 + hc * 32);
            TCG_WAIT_LD();
            int d0 = ch * 64 + hc * 32;
#pragma unroll
            for (int j = 0; j < 32; j += 2) {
                float a0 = (__uint_as_float(tr[j])     + biasf[d0 + j])     * scale;
                float a1 = (__uint_as_float(tr[j + 1]) + biasf[d0 + j + 1]) * scale;
                uint32_t h, l;
                split2(a0, a1, h, l);
                *(uint32_t*)(Ohi + obase + d0 + j) = h;
                *(uint32_t*)(Olo + obase + d0 + j) = l;
            }
        }
        TCG_FENCE_BEFORE();
        GRID_TRIGGER();
    } else {
        uint32_t* ShH = (uint32_t*)(smem + POFF_A);
        uint32_t* ShL = ShH + 128 * VSH_STRIDE;
        float bv_r = biasf[row];
#pragma unroll
        for (int hc = 0; hc < 2; ++hc) {
            uint32_t tr[32];
            TCG_LD_X32(tr, tbase + ch * 64 + hc * 32);
            TCG_WAIT_LD();
#pragma unroll
            for (int j = 0; j < 32; j += 2) {
                float a0 = __uint_as_float(tr[j])     + bv_r;
                float a1 = __uint_as_float(tr[j + 1]) + bv_r;
                uint32_t h, l;
                split2(a0, a1, h, l);
                int col = ch * 32 + hc * 16 + (j >> 1);
                ShH[row * VSH_STRIDE + col] = h;
                ShL[row * VSH_STRIDE + col] = l;
            }
        }
        TCG_FENCE_BEFORE();
        __syncthreads();
        size_t vbase = ((size_t)b * D_) * L_ + l0;
#pragma unroll
        for (int p = 0; p < 8; ++p) {
            int e = tid + p * 256;
            int r = e >> 4, q = e & 15;
            uint4 vh = *(uint4*)&ShH[r * VSH_STRIDE + q * 4];
            uint4 vl = *(uint4*)&ShL[r * VSH_STRIDE + q * 4];
            *(uint4*)(g_Vthi + vbase + (size_t)r * L_ + q * 8) = vh;
            *(uint4*)(g_Vtlo + vbase + (size_t)r * L_ + q * 8) = vl;
        }
        GRID_TRIGGER();
    }

    __syncthreads();
    if (w == 0) {
        if (elect_one()) MBAR_INVAL(sb + 8);
        TCG_RELINQ();
        TCG_DEALLOC(tbase, 128);
    }
#endif
}

// ---------------- tensor-core flash attention (R16 version) -----------------
#define OFF_RED   128
#define OFF_QHI   2048
#define OFF_QLO   (OFF_QHI + 32768)
#define OFF_KHI   (OFF_QLO + 32768)
#define OFF_KLO   (OFF_KHI + 32768)
#define OFF_VHI   (OFF_KLO + 32768)
#define OFF_VLO   (OFF_VHI + 32768)
#define FLASH_SMEM (OFF_VLO + 32768)   // 198656 bytes

#define MB_QK 8
#define MB_PV 16
#define NT 16

__global__ void __launch_bounds__(256, 1) flash_tc_kernel(float* __restrict__ Og) {
#if HAS_TCGEN05
    extern __shared__ char smem[];
    uint32_t sb = smem_u32(smem);
    int tid = threadIdx.x;
    int w = tid >> 5;
    int lane = tid & 31;
    int sub = w & 3;
    int ch = w >> 2;
    int row = sub * 32 + lane;
    int b = blockIdx.y;
    int q0 = blockIdx.x * 128;

    if (w == 0) {
        TCG_ALLOC(sb + 0, 512);
        if (elect_one()) { MBAR_INIT(sb + MB_QK, 1); MBAR_INIT(sb + MB_PV, 1); }
    }
    __syncthreads();
    uint32_t tbase;
    asm volatile("ld.shared.b32 %0, [%1];" : "=r"(tbase) : "r"(sb + 0));
    uint32_t tmem_o = tbase;
    uint32_t tmem_s[2] = {tbase + 128, tbase + 256};
    uint32_t tmem_phi = tbase + 384;
    uint32_t tmem_plo = tbase + 448;
    uint32_t wofs = (uint32_t)sub << 21;

    const int IA[3] = {0, 0, 1}, IB[3] = {0, 1, 0};
    float* redf = (float*)(smem + OFF_RED);
    const __nv_bfloat16* Kgh = g_Khi + (size_t)b * L_ * D_;
    const __nv_bfloat16* Kgl = g_Klo + (size_t)b * L_ * D_;
    size_t vtb = (size_t)b * D_ * L_;

    int rr[8], cc[8];
    uint32_t aa[8];
#pragma unroll
    for (int p = 0; p < 8; ++p) {
        int i = tid + p * 256;
        rr[p] = i >> 4; cc[p] = i & 15;
        aa[p] = blk_addr(rr[p], cc[p], 16);
    }

    GRID_DEP_SYNC();

    {
        size_t qoff = ((size_t)(b * L_ + q0)) * D_;
#pragma unroll
        for (int p = 0; p < 8; ++p) {
            size_t go = (size_t)rr[p] * D_ + cc[p] * 8;
            *(uint4*)(smem + OFF_QHI + aa[p]) = *(const uint4*)(g_Qhi + qoff + go);
            *(uint4*)(smem + OFF_QLO + aa[p]) = *(const uint4*)(g_Qlo + qoff + go);
            *(uint4*)(smem + OFF_KHI + aa[p]) = *(const uint4*)(Kgh + go);
            *(uint4*)(smem + OFF_KLO + aa[p]) = *(const uint4*)(Kgl + go);
            size_t vo = vtb + (size_t)rr[p] * L_ + cc[p] * 8;
            *(uint4*)(smem + OFF_VHI + aa[p]) = *(const uint4*)(g_Vthi + vo);
            *(uint4*)(smem + OFF_VLO + aa[p]) = *(const uint4*)(g_Vtlo + vo);
        }
    }
    FENCE_ASYNC();
    __syncthreads();

    if (w == 0) {
        uint64_t ad[2] = {MK_DESC(sb + OFF_QHI), MK_DESC(sb + OFF_QLO)};
        uint64_t bd[2] = {MK_DESC(sb + OFF_KHI), MK_DESC(sb + OFF_KLO)};
        if (elect_one()) {
            bool acc = false;
#pragma unroll
            for (int p3 = 0; p3 < 3; ++p3)
#pragma unroll
                for (int ks = 0; ks < 8; ++ks) {
                    uint64_t off = (uint64_t)((ks & 3) * 2 + (ks >> 2) * 1024);
                    mma_f16_ss(tmem_s[0], ad[IA[p3]] + off, bd[IB[p3]] + off, IDESC_128, acc);
                    acc = true;
                }
            TCG_COMMIT(sb + MB_QK);
        }
    }

    float l_run = 0.f;

    for (int t = 0; t < NT; ++t) {
        int buf = t & 1, nbuf = buf ^ 1;

        mbar_wait(sb + MB_QK, t & 1);
        TCG_FENCE_AFTER();

        uint4 kh[8], kl[8];
        if (t < NT - 1) {
            size_t koff = (size_t)(t + 1) * 128 * D_;
#pragma unroll
            for (int p = 0; p < 8; ++p) {
                size_t go = koff + (size_t)rr[p] * D_ + cc[p] * 8;
                kh[p] = *(const uint4*)(Kgh + go);
                kl[p] = *(const uint4*)(Kgl + go);
            }
        }

        uint32_t sr[64];
        TCG_LD_X32(sr, tmem_s[buf] + ch * 64);
        TCG_LD_X32(sr + 32, tmem_s[buf] + ch * 64 + 32);

        if (t < NT - 1) {
#pragma unroll
            for (int p = 0; p < 8; ++p) {
                *(uint4*)(smem + OFF_KHI + aa[p]) = kh[p];
                *(uint4*)(smem + OFF_KLO + aa[p]) = kl[p];
            }
        }
        TCG_WAIT_LD();
        TCG_FENCE_BEFORE();
        FENCE_ASYNC();
        __syncthreads();

        if (t < NT - 1 && w == 0) {
            uint64_t ad[2] = {MK_DESC(sb + OFF_QHI), MK_DESC(sb + OFF_QLO)};
            uint64_t bd[2] = {MK_DESC(sb + OFF_KHI), MK_DESC(sb + OFF_KLO)};
            if (elect_one()) {
                bool acc = false;
#pragma unroll
                for (int p3 = 0; p3 < 3; ++p3)
#pragma unroll
                    for (int ks = 0; ks < 8; ++ks) {
                        uint64_t off = (uint64_t)((ks & 3) * 2 + (ks >> 2) * 1024);
                        mma_f16_ss(tmem_s[nbuf], ad[IA[p3]] + off, bd[IB[p3]] + off,
                                   IDESC_128, acc);
                        acc = true;
                    }
                TCG_COMMIT(sb + MB_QK);
            }
        }

        uint4 vh[8], vl[8];
        if (t >= 1) {
            size_t vo0 = vtb + (size_t)t * 128;
#pragma unroll
            for (int p = 0; p < 8; ++p) {
                size_t go = vo0 + (size_t)rr[p] * L_ + cc[p] * 8;
                vh[p] = *(const uint4*)(g_Vthi + go);
                vl[p] = *(const uint4*)(g_Vtlo + go);
            }
        }

        float lsum = 0.f;
        uint32_t hw[32], lw[32];
#pragma unroll
        for (int u = 0; u < 32; ++u) {
            float a0, a1;
            asm("ex2.approx.ftz.f32 %0, %1;" : "=f"(a0) : "f"(__uint_as_float(sr[u * 2])));
            asm("ex2.approx.ftz.f32 %0, %1;" : "=f"(a1) : "f"(__uint_as_float(sr[u * 2 + 1])));
            lsum += a0 + a1;
            split2(a0, a1, hw[u], lw[u]);
        }
        redf[ch * 128 + row] = lsum;

        if (t >= 1) { mbar_wait(sb + MB_PV, (t - 1) & 1); TCG_FENCE_AFTER(); }

        TCG_ST_X32(tmem_phi + ch * 32 + wofs, hw);
        TCG_ST_X32(tmem_plo + ch * 32 + wofs, lw);
        TCG_WAIT_ST();
        TCG_FENCE_BEFORE();

        if (t >= 1) {
#pragma unroll
            for (int p = 0; p < 8; ++p) {
                *(uint4*)(smem + OFF_VHI + aa[p]) = vh[p];
                *(uint4*)(smem + OFF_VLO + aa[p]) = vl[p];
            }
        }
        FENCE_ASYNC();
        __syncthreads();
        l_run += redf[row] + redf[128 + row];

        if (w == 0 && elect_one()) {
            TCG_FENCE_AFTER();
            uint32_t pa[2] = {tmem_phi, tmem_plo};
            uint64_t vd[2] = {MK_DESC(sb + OFF_VHI), MK_DESC(sb + OFF_VLO)};
            bool acc = (t > 0);
#pragma unroll
            for (int p3 = 0; p3 < 3; ++p3)
#pragma unroll
                for (int ks = 0; ks < 8; ++ks) {
                    uint64_t boff = (uint64_t)((ks & 3) * 2 + (ks >> 2) * 1024);
                    mma_f16_ts(tmem_o, pa[IA[p3]] + ks * 8, vd[IB[p3]] + boff,
                               IDESC_128, acc);
                    acc = true;
                }
            TCG_COMMIT(sb + MB_PV);
        }
    }

    mbar_wait(sb + MB_PV, (NT - 1) & 1);
    TCG_FENCE_AFTER();
    {
        float inv = 1.0f / l_run;
        float* Ob = Og + ((size_t)(b * L_ + q0 + row)) * D_ + ch * 64;
        uint32_t tr[32];
        TCG_LD_X32(tr, tmem_o + ch * 64);
        TCG_WAIT_LD();
#pragma unroll
        for (int j = 0; j < 32; j += 4) {
            float4 v;
            v.x = __uint_as_float(tr[j])     * inv;
            v.y = __uint_as_float(tr[j + 1]) * inv;
            v.z = __uint_as_float(tr[j + 2]) * inv;
            v.w = __uint_as_float(tr[j + 3]) * inv;
            *(float4*)&Ob[j] = v;
        }
        TCG_LD_X32(tr, tmem_o + ch * 64 + 32);
        TCG_WAIT_LD();
#pragma unroll
        for (int j = 0; j < 32; j += 4) {
            float4 v;
            v.x = __uint_as_float(tr[j])     * inv;
            v.y = __uint_as_float(tr[j + 1]) * inv;
            v.z = __uint_as_float(tr[j + 2]) * inv;
            v.w = __uint_as_float(tr[j + 3]) * inv;
            *(float4*)&Ob[32 + j] = v;
        }
        TCG_FENCE_BEFORE();
    }

    __syncthreads();
    if (w == 0) {
        if (elect_one()) { MBAR_INVAL(sb + MB_QK); MBAR_INVAL(sb + MB_PV); }
        TCG_RELINQ();
        TCG_DEALLOC(tbase, 512);
    }
#endif  // HAS_TCGEN05
}

extern "C" void kernel_launch(void* const* d_in, const int* in_sizes, int n_in,
                              void* d_out, int out_size) {
    const float* x_inner = (const float*)d_in[0];
    const float* x_outer = (const float*)d_in[1];
    const float* Wq = (const float*)d_in[2];
    const float* bq = (const float*)d_in[3];
    const float* Wk = (const float*)d_in[4];
    const float* bk = (const float*)d_in[5];
    const float* Wv = (const float*)d_in[6];
    const float* bv = (const float*)d_in[7];
    float* out = (float*)d_out;

    cudaFuncSetAttribute(proj_tc_kernel,
                         cudaFuncAttributeMaxDynamicSharedMemorySize, PROJ_SMEM);
    cudaFuncSetAttribute(flash_tc_kernel,
                         cudaFuncAttributeMaxDynamicSharedMemorySize, FLASH_SMEM);

    prep_kernel<<<dim3(D_ * C_ / 512, 3), 256>>>(Wq, Wk, Wv);

    cudaLaunchAttribute pdl[1];
    pdl[0].id = cudaLaunchAttributeProgrammaticStreamSerialization;
    pdl[0].val.programmaticStreamSerializationAllowed = 1;

    {
        cudaLaunchConfig_t cfg = {};
        cfg.gridDim = dim3(L_ / 128, B_, 3);
        cfg.blockDim = dim3(256, 1, 1);
        cfg.dynamicSmemBytes = PROJ_SMEM;
        cfg.stream = 0;
        cfg.attrs = pdl;
        cfg.numAttrs = 1;
        cudaLaunchKernelEx(&cfg, proj_tc_kernel, x_inner, x_outer, bq, bk, bv);
    }
    {
        cudaLaunchConfig_t cfg = {};
        cfg.gridDim = dim3(L_ / 128, B_, 1);
        cfg.blockDim = dim3(256, 1, 1);
        cfg.dynamicSmemBytes = FLASH_SMEM;
        cfg.stream = 0;
        cfg.attrs = pdl;
        cfg.numAttrs = 1;
        cudaLaunchKernelEx(&cfg, flash_tc_kernel, out);
    }
}